// round 2
// baseline (speedup 1.0000x reference)
#include <cuda_runtime.h>
#include <cuda_bf16.h>
#include <math.h>

// Problem constants
#define BB 2
#define SS 1024
#define DD 768
#define HH 12
#define HDIM 64
#define EE 8
#define TOPK 2
#define FF 3072
#define NTOK (BB*SS)        // 2048
#define D3 (3*DD)           // 2304
#define NPAIR (NTOK*TOPK)   // 4096

// ---------------- device scratch (no allocations allowed) ----------------
__device__ float g_xln1[NTOK*DD];
__device__ float g_qkv [NTOK*D3];
__device__ float g_ctx [NTOK*DD];
__device__ float g_hs  [NTOK*DD];
__device__ float g_x2  [NTOK*DD];
__device__ float g_h   [NPAIR*FF];       // gelu(fc) activations per (token,slot)
__device__ int   g_topidx[NTOK*TOPK];
__device__ float g_topw [NTOK*TOPK];
__device__ int   g_counts[EE];
__device__ int   g_offsets[EE+1];
__device__ int   g_cursor[EE];
__device__ int   g_pairtok[NPAIR];
__device__ float g_pairw [NPAIR];

// ---------------- LayerNorm: one block per row, D=768 ----------------
__global__ void ln_kernel(const float* __restrict__ x,
                          const float* __restrict__ g,
                          const float* __restrict__ b,
                          float* __restrict__ out) {
    int row = blockIdx.x;
    int tid = threadIdx.x;               // 256 threads, 3 elems each
    const float* xr = x + (size_t)row*DD;
    float v[3];
    float s = 0.f, s2 = 0.f;
#pragma unroll
    for (int i = 0; i < 3; i++) {
        v[i] = xr[tid + i*256];
        s += v[i]; s2 += v[i]*v[i];
    }
    __shared__ float2 red[256];
    red[tid] = make_float2(s, s2);
    __syncthreads();
    for (int off = 128; off > 0; off >>= 1) {
        if (tid < off) {
            red[tid].x += red[tid+off].x;
            red[tid].y += red[tid+off].y;
        }
        __syncthreads();
    }
    float mu  = red[0].x * (1.0f/DD);
    float var = red[0].y * (1.0f/DD) - mu*mu;
    float inv = rsqrtf(var + 1e-5f);
    float* orow = out + (size_t)row*DD;
#pragma unroll
    for (int i = 0; i < 3; i++) {
        int c = tid + i*256;
        orow[c] = (v[i] - mu) * inv * g[c] + b[c];
    }
}

// ---------------- Generic tiled GEMM: C = A[MxK] * B[KxN] (+bias)(+resid) ----------------
// block 16x16, tile 64x64, ktile 16, 4x4 per thread
__global__ void gemm_kernel(const float* __restrict__ A, const float* __restrict__ Bm,
                            const float* __restrict__ bias, const float* __restrict__ resid,
                            float* __restrict__ C, int M, int N, int K) {
    __shared__ float As[16][65];   // As[kk][m]
    __shared__ float Bs[16][64];   // Bs[kk][n]
    int tx = threadIdx.x, ty = threadIdx.y;
    int tid = ty*16 + tx;
    int rowBase = blockIdx.y*64;
    int colBase = blockIdx.x*64;
    float acc[4][4] = {};
    for (int k0 = 0; k0 < K; k0 += 16) {
#pragma unroll
        for (int l = 0; l < 4; l++) {
            int idx = tid + l*256;
            int m = idx >> 4, kk = idx & 15;
            int r = rowBase + m;
            As[kk][m] = (r < M) ? A[(size_t)r*K + k0 + kk] : 0.f;
        }
#pragma unroll
        for (int l = 0; l < 4; l++) {
            int idx = tid + l*256;
            int kk = idx >> 6, nn = idx & 63;
            Bs[kk][nn] = Bm[(size_t)(k0+kk)*N + colBase + nn];
        }
        __syncthreads();
#pragma unroll
        for (int kk = 0; kk < 16; kk++) {
            float a[4], bv[4];
#pragma unroll
            for (int i = 0; i < 4; i++) a[i]  = As[kk][ty*4+i];
#pragma unroll
            for (int j = 0; j < 4; j++) bv[j] = Bs[kk][tx*4+j];
#pragma unroll
            for (int i = 0; i < 4; i++)
#pragma unroll
                for (int j = 0; j < 4; j++)
                    acc[i][j] += a[i]*bv[j];
        }
        __syncthreads();
    }
#pragma unroll
    for (int i = 0; i < 4; i++) {
        int r = rowBase + ty*4 + i;
        if (r >= M) continue;
#pragma unroll
        for (int j = 0; j < 4; j++) {
            int c = colBase + tx*4 + j;
            float v = acc[i][j];
            if (bias)  v += bias[c];
            if (resid) v += resid[(size_t)r*N + c];
            C[(size_t)r*N + c] = v;
        }
    }
}

// ---------------- Attention: one block per (q, b*h), 64 threads, online softmax ----------------
__global__ void attn_kernel() {
    __shared__ float sQ[64];
    __shared__ float sK[64][65];
    __shared__ float sV[64][65];
    __shared__ float sS[64];
    __shared__ float sP[64];
    int t  = threadIdx.x;          // 0..63 : owns output dim t
    int q  = blockIdx.x;
    int bh = blockIdx.y;
    int b  = bh / HH, h = bh % HH;
    const float* qrow = g_qkv + ((size_t)(b*SS + q))*D3 + h*HDIM;
    sQ[t] = qrow[t] * 0.125f;      // 1/sqrt(64)
    float m = -1e30f, l = 0.f, acc = 0.f;
    int nk = q + 1;
    for (int kt = 0; kt < nk; kt += 64) {
        int tlen = min(64, nk - kt);
        for (int j = 0; j < tlen; j++) {
            const float* krow = g_qkv + ((size_t)(b*SS + kt + j))*D3 + DD + h*HDIM;
            sK[j][t] = krow[t];
            sV[j][t] = krow[DD + t];   // V lives at row_start + 2*DD + h*HDIM + t
        }
        __syncthreads();
        float sc = -1e30f;
        if (t < tlen) {
            sc = 0.f;
#pragma unroll 16
            for (int d = 0; d < 64; d++) sc += sQ[d]*sK[t][d];
        }
        sS[t] = sc;
        __syncthreads();
        float tm = -1e30f;
        for (int j = 0; j < tlen; j++) tm = fmaxf(tm, sS[j]);
        float nm = fmaxf(m, tm);
        float scale = expf(m - nm);
        float pv = (t < tlen) ? expf(sS[t] - nm) : 0.f;
        sP[t] = pv;
        __syncthreads();
        float la = 0.f, aa = 0.f;
        for (int j = 0; j < tlen; j++) {
            float p = sP[j];
            la += p;
            aa += p * sV[j][t];
        }
        l   = l*scale + la;
        acc = acc*scale + aa;
        m = nm;
        __syncthreads();
    }
    g_ctx[((size_t)(b*SS + q))*DD + h*HDIM + t] = acc / l;
}

// ---------------- Router + top-2 ----------------
__global__ void router_kernel(const float* __restrict__ x2, const float* __restrict__ w_router) {
    int gid  = blockIdx.x*blockDim.x + threadIdx.x;
    int warp = gid >> 5;
    int lane = gid & 31;
    if (warp >= NTOK) return;
    float p[EE] = {};
    const float* xr = x2 + (size_t)warp*DD;
    for (int d = lane; d < DD; d += 32) {
        float xv = xr[d];
#pragma unroll
        for (int e = 0; e < EE; e++) p[e] += xv * w_router[e*DD + d];
    }
#pragma unroll
    for (int off = 16; off > 0; off >>= 1)
#pragma unroll
        for (int e = 0; e < EE; e++)
            p[e] += __shfl_down_sync(0xffffffffu, p[e], off);
    if (lane == 0) {
        float mx = p[0];
#pragma unroll
        for (int e = 1; e < EE; e++) mx = fmaxf(mx, p[e]);
        float ex[EE];
#pragma unroll
        for (int e = 0; e < EE; e++) ex[e] = expf(p[e] - mx);
        int i0 = 0;
#pragma unroll
        for (int e = 1; e < EE; e++) if (ex[e] > ex[i0]) i0 = e;
        int i1 = (i0 == 0) ? 1 : 0;
#pragma unroll
        for (int e = 0; e < EE; e++) if (e != i0 && ex[e] > ex[i1]) i1 = e;
        float denom = ex[i0] + ex[i1];
        g_topidx[warp*2+0] = i0;  g_topw[warp*2+0] = ex[i0]/denom;
        g_topidx[warp*2+1] = i1;  g_topw[warp*2+1] = ex[i1]/denom;
        atomicAdd(&g_counts[i0], 1);
        atomicAdd(&g_counts[i1], 1);
    }
}

__global__ void offsets_kernel() {
    g_offsets[0] = 0;
    for (int e = 0; e < EE; e++) {
        g_offsets[e+1] = g_offsets[e] + g_counts[e];
        g_cursor[e] = 0;
    }
}

__global__ void fill_kernel() {
    int t = blockIdx.x*blockDim.x + threadIdx.x;
    if (t >= NTOK) return;
#pragma unroll
    for (int k = 0; k < TOPK; k++) {
        int e = g_topidx[t*2+k];
        int pos = g_offsets[e] + atomicAdd(&g_cursor[e], 1);
        g_pairtok[pos] = t;
        g_pairw[pos]   = g_topw[t*2+k];
    }
}

// ---------------- MoE FC: h = gelu(x2_gathered @ w_fc[e] + b_fc[e]) ----------------
__global__ void moe_fc_kernel(const float* __restrict__ x2,
                              const float* __restrict__ w_fc,
                              const float* __restrict__ b_fc) {
    int e = blockIdx.z;
    int seg = g_offsets[e];
    int cnt = g_offsets[e+1] - seg;
    int rowBase = blockIdx.y*64;
    if (rowBase >= cnt) return;
    int colBase = blockIdx.x*64;
    __shared__ float As[16][65];
    __shared__ float Bs[16][64];
    __shared__ int sTok[64];
    int tx = threadIdx.x, ty = threadIdx.y;
    int tid = ty*16 + tx;
    if (tid < 64)
        sTok[tid] = (rowBase + tid < cnt) ? g_pairtok[seg + rowBase + tid] : -1;
    __syncthreads();
    const float* Bm = w_fc + (size_t)e*DD*FF;
    float acc[4][4] = {};
    for (int k0 = 0; k0 < DD; k0 += 16) {
#pragma unroll
        for (int l = 0; l < 4; l++) {
            int idx = tid + l*256;
            int m = idx >> 4, kk = idx & 15;
            int tk = sTok[m];
            As[kk][m] = (tk >= 0) ? x2[(size_t)tk*DD + k0 + kk] : 0.f;
        }
#pragma unroll
        for (int l = 0; l < 4; l++) {
            int idx = tid + l*256;
            int kk = idx >> 6, nn = idx & 63;
            Bs[kk][nn] = Bm[(size_t)(k0+kk)*FF + colBase + nn];
        }
        __syncthreads();
#pragma unroll
        for (int kk = 0; kk < 16; kk++) {
            float a[4], bv[4];
#pragma unroll
            for (int i = 0; i < 4; i++) a[i]  = As[kk][ty*4+i];
#pragma unroll
            for (int j = 0; j < 4; j++) bv[j] = Bs[kk][tx*4+j];
#pragma unroll
            for (int i = 0; i < 4; i++)
#pragma unroll
                for (int j = 0; j < 4; j++)
                    acc[i][j] += a[i]*bv[j];
        }
        __syncthreads();
    }
#pragma unroll
    for (int i = 0; i < 4; i++) {
        int rl = rowBase + ty*4 + i;
        if (rl >= cnt) continue;
        size_t p = (size_t)(seg + rl);
#pragma unroll
        for (int j = 0; j < 4; j++) {
            int c = colBase + tx*4 + j;
            float v = acc[i][j] + b_fc[e*FF + c];
            // exact gelu: 0.5*x*(1+erf(x/sqrt(2)))
            v = 0.5f * v * (1.0f + erff(v * 0.70710678118654752f));
            g_h[p*FF + c] = v;
        }
    }
}

// ---------------- MoE PROJ: out += gate * (h @ w_proj[e] + b_proj[e]) ----------------
__global__ void moe_proj_kernel(const float* __restrict__ w_proj,
                                const float* __restrict__ b_proj,
                                float* __restrict__ out) {
    int e = blockIdx.z;
    int seg = g_offsets[e];
    int cnt = g_offsets[e+1] - seg;
    int rowBase = blockIdx.y*64;
    if (rowBase >= cnt) return;
    int colBase = blockIdx.x*64;
    __shared__ float As[16][65];
    __shared__ float Bs[16][64];
    int tx = threadIdx.x, ty = threadIdx.y;
    int tid = ty*16 + tx;
    const float* Bm = w_proj + (size_t)e*FF*DD;
    float acc[4][4] = {};
    for (int k0 = 0; k0 < FF; k0 += 16) {
#pragma unroll
        for (int l = 0; l < 4; l++) {
            int idx = tid + l*256;
            int m = idx >> 4, kk = idx & 15;
            int rl = rowBase + m;
            As[kk][m] = (rl < cnt) ? g_h[(size_t)(seg+rl)*FF + k0 + kk] : 0.f;
        }
#pragma unroll
        for (int l = 0; l < 4; l++) {
            int idx = tid + l*256;
            int kk = idx >> 6, nn = idx & 63;
            Bs[kk][nn] = Bm[(size_t)(k0+kk)*DD + colBase + nn];
        }
        __syncthreads();
#pragma unroll
        for (int kk = 0; kk < 16; kk++) {
            float a[4], bv[4];
#pragma unroll
            for (int i = 0; i < 4; i++) a[i]  = As[kk][ty*4+i];
#pragma unroll
            for (int j = 0; j < 4; j++) bv[j] = Bs[kk][tx*4+j];
#pragma unroll
            for (int i = 0; i < 4; i++)
#pragma unroll
                for (int j = 0; j < 4; j++)
                    acc[i][j] += a[i]*bv[j];
        }
        __syncthreads();
    }
#pragma unroll
    for (int i = 0; i < 4; i++) {
        int rl = rowBase + ty*4 + i;
        if (rl >= cnt) continue;
        int p = seg + rl;
        int tok = g_pairtok[p];
        float pw = g_pairw[p];
#pragma unroll
        for (int j = 0; j < 4; j++) {
            int c = colBase + tx*4 + j;
            float v = pw * (acc[i][j] + b_proj[e*DD + c]);
            atomicAdd(&out[(size_t)tok*DD + c], v);
        }
    }
}

// ---------------- launch ----------------
extern "C" void kernel_launch(void* const* d_in, const int* in_sizes, int n_in,
                              void* d_out, int out_size) {
    const float* hidden     = (const float*)d_in[0];
    const float* ln1_g      = (const float*)d_in[1];
    const float* ln1_b      = (const float*)d_in[2];
    const float* w_attn     = (const float*)d_in[3];
    const float* b_attn     = (const float*)d_in[4];
    const float* w_attnproj = (const float*)d_in[5];
    const float* b_attnproj = (const float*)d_in[6];
    const float* ln2_g      = (const float*)d_in[7];
    const float* ln2_b      = (const float*)d_in[8];
    const float* w_router   = (const float*)d_in[9];
    const float* w_fc       = (const float*)d_in[10];
    const float* b_fc       = (const float*)d_in[11];
    const float* w_proj     = (const float*)d_in[12];
    const float* b_proj     = (const float*)d_in[13];
    float* out = (float*)d_out;

    float *xln1, *qkv, *ctx, *hs, *x2;
    int* counts;
    cudaGetSymbolAddress((void**)&xln1,   g_xln1);
    cudaGetSymbolAddress((void**)&qkv,    g_qkv);
    cudaGetSymbolAddress((void**)&ctx,    g_ctx);
    cudaGetSymbolAddress((void**)&hs,     g_hs);
    cudaGetSymbolAddress((void**)&x2,     g_x2);
    cudaGetSymbolAddress((void**)&counts, g_counts);

    dim3 blk(16,16);

    // attention sub-block
    ln_kernel<<<NTOK, 256>>>(hidden, ln1_g, ln1_b, xln1);
    gemm_kernel<<<dim3(D3/64, NTOK/64), blk>>>(xln1, w_attn, b_attn, nullptr, qkv, NTOK, D3, DD);
    attn_kernel<<<dim3(SS, BB*HH), 64>>>();
    gemm_kernel<<<dim3(DD/64, NTOK/64), blk>>>(ctx, w_attnproj, b_attnproj, hidden, hs, NTOK, DD, DD);

    // out starts as residual (hs); MoE accumulates into it
    cudaMemcpyAsync(out, hs, (size_t)NTOK*DD*sizeof(float), cudaMemcpyDeviceToDevice);

    // MoE sub-block
    ln_kernel<<<NTOK, 256>>>(hs, ln2_g, ln2_b, x2);
    cudaMemsetAsync(counts, 0, EE*sizeof(int));
    router_kernel<<<(NTOK*32)/256, 256>>>(x2, w_router);
    offsets_kernel<<<1,1>>>();
    fill_kernel<<<NTOK/256, 256>>>();
    moe_fc_kernel<<<dim3(FF/64, NPAIR/64, EE), blk>>>(x2, w_fc, b_fc);
    moe_proj_kernel<<<dim3(DD/64, NPAIR/64, EE), blk>>>(w_proj, b_proj, out);
}

// round 3
// speedup vs baseline: 3.5023x; 3.5023x over previous
#include <cuda_runtime.h>
#include <cuda_bf16.h>
#include <math.h>

// Problem constants
#define BB 2
#define SS 1024
#define DD 768
#define HH 12
#define HDIM 64
#define EE 8
#define TOPK 2
#define FF 3072
#define NTOK (BB*SS)        // 2048
#define D3 (3*DD)           // 2304
#define NPAIR (NTOK*TOPK)   // 4096

// ---------------- device scratch ----------------
__device__ float g_xln1[NTOK*DD];
__device__ float g_qkv [NTOK*D3];
__device__ float g_ctx [NTOK*DD];
__device__ float g_hs  [NTOK*DD];
__device__ float g_x2  [NTOK*DD];
__device__ float g_h   [NPAIR*FF];
__device__ int   g_topidx[NTOK*TOPK];
__device__ float g_topw [NTOK*TOPK];
__device__ int   g_counts[EE];
__device__ int   g_offsets[EE+1];
__device__ int   g_cursor[EE];
__device__ int   g_pairtok[NPAIR];
__device__ float g_pairw [NPAIR];

// ---------------- helpers ----------------
__device__ __forceinline__ unsigned f2tf32(float x) {
    unsigned u;
    asm("cvt.rna.tf32.f32 %0, %1;" : "=r"(u) : "f"(x));
    return u;
}
__device__ __forceinline__ void mma_tf32(float c[4], unsigned a0, unsigned a1,
                                         unsigned a2, unsigned a3,
                                         unsigned b0, unsigned b1) {
    asm volatile(
        "mma.sync.aligned.m16n8k8.row.col.f32.tf32.tf32.f32 "
        "{%0,%1,%2,%3},{%4,%5,%6,%7},{%8,%9},{%0,%1,%2,%3};"
        : "+f"(c[0]), "+f"(c[1]), "+f"(c[2]), "+f"(c[3])
        : "r"(a0), "r"(a1), "r"(a2), "r"(a3), "r"(b0), "r"(b1));
}

// ---------------- LayerNorm ----------------
__global__ void ln_kernel(const float* __restrict__ x,
                          const float* __restrict__ g,
                          const float* __restrict__ b,
                          float* __restrict__ out) {
    int row = blockIdx.x;
    int tid = threadIdx.x;
    const float* xr = x + (size_t)row*DD;
    float v[3];
    float s = 0.f, s2 = 0.f;
#pragma unroll
    for (int i = 0; i < 3; i++) {
        v[i] = xr[tid + i*256];
        s += v[i]; s2 += v[i]*v[i];
    }
    __shared__ float2 red[256];
    red[tid] = make_float2(s, s2);
    __syncthreads();
    for (int off = 128; off > 0; off >>= 1) {
        if (tid < off) {
            red[tid].x += red[tid+off].x;
            red[tid].y += red[tid+off].y;
        }
        __syncthreads();
    }
    float mu  = red[0].x * (1.0f/DD);
    float var = red[0].y * (1.0f/DD) - mu*mu;
    float inv = rsqrtf(var + 1e-5f);
    float* orow = out + (size_t)row*DD;
#pragma unroll
    for (int i = 0; i < 3; i++) {
        int c = tid + i*256;
        orow[c] = (v[i] - mu) * inv * g[c] + b[c];
    }
}

// ---------------- TF32 MMA GEMM (templated epilogue/gather) ----------------
// MODE 0: C = A@B + bias                        (QKV)
// MODE 1: C = A@B + bias + resid                (attn out proj)
// MODE 2: C = gelu(gather(A)@B[e] + bias[e])    (MoE FC, write g_h)
// MODE 3: atomic C[tok] += w * (A@B[e]+bias[e]) (MoE PROJ)
// block: 256 threads = 8 warps (2 m x 4 n), block tile 128x128, k-step 16
template<int MODE>
__global__ void __launch_bounds__(256)
mma_gemm(const float* __restrict__ A, const float* __restrict__ B,
         const float* __restrict__ bias, const float* __restrict__ resid,
         float* __restrict__ C, int M, int N, int K) {
    int e = 0, seg = 0, cnt = M;
    if (MODE >= 2) {
        e = blockIdx.z;
        seg = g_offsets[e];
        cnt = g_offsets[e+1] - seg;
    }
    int rowBase = blockIdx.y * 128;
    if (rowBase >= cnt) return;
    int colBase = blockIdx.x * 128;
    const float* Bm = B + (size_t)e*K*N;
    const float* biasv = bias + (size_t)e*N;

    __shared__ unsigned As[128][20];   // [m][k], pad 20 -> conflict-free frag loads
    __shared__ unsigned Bs[16][136];   // [k][n], pad 136 -> conflict-free frag loads
    __shared__ int sTok[128];

    int tid = threadIdx.x;
    int lane = tid & 31, warp = tid >> 5;
    int wy = warp >> 2, wx = warp & 3;   // warp tile: rows wy*64, cols wx*32
    int g4 = lane >> 2, t4 = lane & 3;

    if (MODE == 2) {
        if (tid < 128)
            sTok[tid] = (rowBase + tid < cnt) ? g_pairtok[seg + rowBase + tid] : -1;
        __syncthreads();
    }

    float acc[4][4][4] = {};

    for (int k0 = 0; k0 < K; k0 += 16) {
        if (k0) __syncthreads();
        // fill A tile (tf32 converted)
#pragma unroll
        for (int l = 0; l < 2; l++) {
            int idx = tid + l*256;
            int r = idx >> 2, kq = (idx & 3) * 4;
            float4 v = make_float4(0.f, 0.f, 0.f, 0.f);
            if (MODE == 2) {
                int tk = sTok[r];
                if (tk >= 0) v = *(const float4*)&A[(size_t)tk*K + k0 + kq];
            } else if (MODE == 3) {
                if (rowBase + r < cnt)
                    v = *(const float4*)&A[(size_t)(seg + rowBase + r)*K + k0 + kq];
            } else {
                if (rowBase + r < M)
                    v = *(const float4*)&A[(size_t)(rowBase + r)*K + k0 + kq];
            }
            uint4 u = make_uint4(f2tf32(v.x), f2tf32(v.y), f2tf32(v.z), f2tf32(v.w));
            *(uint4*)&As[r][kq] = u;
        }
        // fill B tile
#pragma unroll
        for (int l = 0; l < 2; l++) {
            int idx = tid + l*256;
            int br = idx >> 5, c4 = (idx & 31) * 4;
            float4 v = *(const float4*)&Bm[(size_t)(k0 + br)*N + colBase + c4];
            uint4 u = make_uint4(f2tf32(v.x), f2tf32(v.y), f2tf32(v.z), f2tf32(v.w));
            *(uint4*)&Bs[br][c4] = u;
        }
        __syncthreads();
        // compute: 2 k-steps of 8
#pragma unroll
        for (int ks = 0; ks < 16; ks += 8) {
            unsigned af[4][4];
#pragma unroll
            for (int mi = 0; mi < 4; mi++) {
                int r = wy*64 + mi*16 + g4;
                int kc = ks + t4;
                af[mi][0] = As[r][kc];
                af[mi][1] = As[r+8][kc];
                af[mi][2] = As[r][kc+4];
                af[mi][3] = As[r+8][kc+4];
            }
            unsigned bf[4][2];
#pragma unroll
            for (int ni = 0; ni < 4; ni++) {
                int cc = wx*32 + ni*8 + g4;
                bf[ni][0] = Bs[ks + t4][cc];
                bf[ni][1] = Bs[ks + t4 + 4][cc];
            }
#pragma unroll
            for (int mi = 0; mi < 4; mi++)
#pragma unroll
                for (int ni = 0; ni < 4; ni++)
                    mma_tf32(acc[mi][ni], af[mi][0], af[mi][1], af[mi][2], af[mi][3],
                             bf[ni][0], bf[ni][1]);
        }
    }

    // epilogue
#pragma unroll
    for (int mi = 0; mi < 4; mi++) {
#pragma unroll
        for (int ci = 0; ci < 2; ci++) {
            int r = wy*64 + mi*16 + g4 + ci*8;    // local row in tile
            int grow = rowBase + r;               // row within M (modes 0/1) or segment (2/3)
            if (grow >= cnt) continue;
#pragma unroll
            for (int ni = 0; ni < 4; ni++) {
                int col = colBase + wx*32 + ni*8 + t4*2;
                float v0 = acc[mi][ni][ci*2 + 0];
                float v1 = acc[mi][ni][ci*2 + 1];
                if (MODE == 0) {
                    v0 += biasv[col]; v1 += biasv[col+1];
                    *(float2*)&C[(size_t)grow*N + col] = make_float2(v0, v1);
                } else if (MODE == 1) {
                    const float2 rr = *(const float2*)&resid[(size_t)grow*N + col];
                    v0 += biasv[col]   + rr.x;
                    v1 += biasv[col+1] + rr.y;
                    *(float2*)&C[(size_t)grow*N + col] = make_float2(v0, v1);
                } else if (MODE == 2) {
                    v0 += biasv[col]; v1 += biasv[col+1];
                    v0 = 0.5f*v0*(1.0f + erff(v0*0.70710678118654752f));
                    v1 = 0.5f*v1*(1.0f + erff(v1*0.70710678118654752f));
                    *(float2*)&C[(size_t)(seg + grow)*N + col] = make_float2(v0, v1);
                } else {
                    int p = seg + grow;
                    int tok = g_pairtok[p];
                    float pw = g_pairw[p];
                    atomicAdd(&C[(size_t)tok*N + col],   pw*(v0 + biasv[col]));
                    atomicAdd(&C[(size_t)tok*N + col+1], pw*(v1 + biasv[col+1]));
                }
            }
        }
    }
}

// ---------------- Attention v2: block per (64-query tile, b*h) ----------------
// 256 threads (16x16), each thread owns a 4x4 patch. Online softmax.
// dynamic smem: Qt[64d][68r], Kt[64d][68r], V[64j][68d], S/P[64r][68j]
__global__ void __launch_bounds__(256) attn_kernel2() {
    extern __shared__ float sm[];
    float* sQt = sm;            // [d*68 + r]
    float* sKt = sm + 4352;     // [d*68 + j]
    float* sV  = sm + 8704;     // [j*68 + d]
    float* sS  = sm + 13056;    // [r*68 + j]

    int tx = threadIdx.x, ty = threadIdx.y;
    int tid = ty*16 + tx;
    int qt = (gridDim.x - 1) - blockIdx.x;    // heavy tiles first
    int bh = blockIdx.y;
    int b = bh / HH, h = bh % HH;
    size_t qkvBase = (size_t)(b*SS)*D3 + h*HDIM;

    // load Q tile transposed, scaled
#pragma unroll
    for (int l = 0; l < 4; l++) {
        int idx = tid + l*256;
        int r = idx >> 4, d4 = (idx & 15) * 4;
        float4 v = *(const float4*)&g_qkv[qkvBase + (size_t)(qt*64 + r)*D3 + d4];
        sQt[(d4+0)*68 + r] = v.x * 0.125f;
        sQt[(d4+1)*68 + r] = v.y * 0.125f;
        sQt[(d4+2)*68 + r] = v.z * 0.125f;
        sQt[(d4+3)*68 + r] = v.w * 0.125f;
    }

    float m[4], l[4], o[4][4];
#pragma unroll
    for (int i = 0; i < 4; i++) {
        m[i] = -1e30f; l[i] = 0.f;
#pragma unroll
        for (int j = 0; j < 4; j++) o[i][j] = 0.f;
    }

    for (int kt = 0; kt <= qt; kt++) {
        __syncthreads();    // prev iteration's PV done
        // load K (transposed) and V tiles
#pragma unroll
        for (int lq = 0; lq < 4; lq++) {
            int idx = tid + lq*256;
            int r = idx >> 4, d4 = (idx & 15) * 4;
            size_t rowp = qkvBase + (size_t)(kt*64 + r)*D3;
            float4 kv = *(const float4*)&g_qkv[rowp + DD + d4];
            sKt[(d4+0)*68 + r] = kv.x;
            sKt[(d4+1)*68 + r] = kv.y;
            sKt[(d4+2)*68 + r] = kv.z;
            sKt[(d4+3)*68 + r] = kv.w;
            float4 vv = *(const float4*)&g_qkv[rowp + 2*DD + d4];
            *(float4*)&sV[r*68 + d4] = vv;
        }
        __syncthreads();

        // S = Q K^T (4x4 per thread)
        float s[4][4] = {};
#pragma unroll 8
        for (int d = 0; d < 64; d++) {
            float4 a4 = *(const float4*)&sQt[d*68 + ty*4];
            float4 b4 = *(const float4*)&sKt[d*68 + tx*4];
            float a[4] = {a4.x, a4.y, a4.z, a4.w};
            float bb[4] = {b4.x, b4.y, b4.z, b4.w};
#pragma unroll
            for (int i = 0; i < 4; i++)
#pragma unroll
                for (int j = 0; j < 4; j++)
                    s[i][j] += a[i]*bb[j];
        }
        // causal mask on diagonal tile
        bool diag = (kt == qt);
        if (diag) {
#pragma unroll
            for (int i = 0; i < 4; i++)
#pragma unroll
                for (int j = 0; j < 4; j++)
                    if (tx*4 + j > ty*4 + i) s[i][j] = -1e30f;
        }
        // online softmax per row (reduce across tx via shuffles, lanes (ty&1)*16+tx)
#pragma unroll
        for (int i = 0; i < 4; i++) {
            float rm = fmaxf(fmaxf(s[i][0], s[i][1]), fmaxf(s[i][2], s[i][3]));
#pragma unroll
            for (int off = 8; off >= 1; off >>= 1)
                rm = fmaxf(rm, __shfl_xor_sync(0xffffffffu, rm, off));
            float nm = fmaxf(m[i], rm);
            float sc = __expf(m[i] - nm);
            float p0 = __expf(s[i][0] - nm);
            float p1 = __expf(s[i][1] - nm);
            float p2 = __expf(s[i][2] - nm);
            float p3 = __expf(s[i][3] - nm);
            float ps = p0 + p1 + p2 + p3;
#pragma unroll
            for (int off = 8; off >= 1; off >>= 1)
                ps += __shfl_xor_sync(0xffffffffu, ps, off);
            l[i] = l[i]*sc + ps;
            m[i] = nm;
#pragma unroll
            for (int j = 0; j < 4; j++) o[i][j] *= sc;
            *(float4*)&sS[(ty*4+i)*68 + tx*4] = make_float4(p0, p1, p2, p3);
        }
        __syncthreads();

        // O += P V
#pragma unroll 4
        for (int j4 = 0; j4 < 16; j4++) {
            float p[4][4];
#pragma unroll
            for (int i = 0; i < 4; i++) {
                float4 t = *(const float4*)&sS[(ty*4+i)*68 + j4*4];
                p[i][0] = t.x; p[i][1] = t.y; p[i][2] = t.z; p[i][3] = t.w;
            }
#pragma unroll
            for (int jj = 0; jj < 4; jj++) {
                float4 v4 = *(const float4*)&sV[(j4*4+jj)*68 + tx*4];
                float vv[4] = {v4.x, v4.y, v4.z, v4.w};
#pragma unroll
                for (int i = 0; i < 4; i++)
#pragma unroll
                    for (int d = 0; d < 4; d++)
                        o[i][d] += p[i][jj]*vv[d];
            }
        }
    }

    // write ctx
#pragma unroll
    for (int i = 0; i < 4; i++) {
        float inv = 1.0f / l[i];
        float4 o4 = make_float4(o[i][0]*inv, o[i][1]*inv, o[i][2]*inv, o[i][3]*inv);
        *(float4*)&g_ctx[(size_t)(b*SS + qt*64 + ty*4 + i)*DD + h*HDIM + tx*4] = o4;
    }
}

// ---------------- Router + top-2 ----------------
__global__ void router_kernel(const float* __restrict__ x2, const float* __restrict__ w_router) {
    int gid  = blockIdx.x*blockDim.x + threadIdx.x;
    int warp = gid >> 5;
    int lane = gid & 31;
    if (warp >= NTOK) return;
    float p[EE] = {};
    const float* xr = x2 + (size_t)warp*DD;
    for (int d = lane; d < DD; d += 32) {
        float xv = xr[d];
#pragma unroll
        for (int e = 0; e < EE; e++) p[e] += xv * w_router[e*DD + d];
    }
#pragma unroll
    for (int off = 16; off > 0; off >>= 1)
#pragma unroll
        for (int e = 0; e < EE; e++)
            p[e] += __shfl_down_sync(0xffffffffu, p[e], off);
    if (lane == 0) {
        float mx = p[0];
#pragma unroll
        for (int e = 1; e < EE; e++) mx = fmaxf(mx, p[e]);
        float ex[EE];
#pragma unroll
        for (int e = 0; e < EE; e++) ex[e] = expf(p[e] - mx);
        int i0 = 0;
#pragma unroll
        for (int e = 1; e < EE; e++) if (ex[e] > ex[i0]) i0 = e;
        int i1 = (i0 == 0) ? 1 : 0;
#pragma unroll
        for (int e = 0; e < EE; e++) if (e != i0 && ex[e] > ex[i1]) i1 = e;
        float denom = ex[i0] + ex[i1];
        g_topidx[warp*2+0] = i0;  g_topw[warp*2+0] = ex[i0]/denom;
        g_topidx[warp*2+1] = i1;  g_topw[warp*2+1] = ex[i1]/denom;
        atomicAdd(&g_counts[i0], 1);
        atomicAdd(&g_counts[i1], 1);
    }
}

__global__ void offsets_kernel() {
    g_offsets[0] = 0;
    for (int e = 0; e < EE; e++) {
        g_offsets[e+1] = g_offsets[e] + g_counts[e];
        g_cursor[e] = 0;
    }
}

__global__ void fill_kernel() {
    int t = blockIdx.x*blockDim.x + threadIdx.x;
    if (t >= NTOK) return;
#pragma unroll
    for (int k = 0; k < TOPK; k++) {
        int e = g_topidx[t*2+k];
        int pos = g_offsets[e] + atomicAdd(&g_cursor[e], 1);
        g_pairtok[pos] = t;
        g_pairw[pos]   = g_topw[t*2+k];
    }
}

// ---------------- launch ----------------
extern "C" void kernel_launch(void* const* d_in, const int* in_sizes, int n_in,
                              void* d_out, int out_size) {
    const float* hidden     = (const float*)d_in[0];
    const float* ln1_g      = (const float*)d_in[1];
    const float* ln1_b      = (const float*)d_in[2];
    const float* w_attn     = (const float*)d_in[3];
    const float* b_attn     = (const float*)d_in[4];
    const float* w_attnproj = (const float*)d_in[5];
    const float* b_attnproj = (const float*)d_in[6];
    const float* ln2_g      = (const float*)d_in[7];
    const float* ln2_b      = (const float*)d_in[8];
    const float* w_router   = (const float*)d_in[9];
    const float* w_fc       = (const float*)d_in[10];
    const float* b_fc       = (const float*)d_in[11];
    const float* w_proj     = (const float*)d_in[12];
    const float* b_proj     = (const float*)d_in[13];
    float* out = (float*)d_out;

    float *xln1, *qkv, *ctx, *hs, *x2;
    int* counts;
    cudaGetSymbolAddress((void**)&xln1,   g_xln1);
    cudaGetSymbolAddress((void**)&qkv,    g_qkv);
    cudaGetSymbolAddress((void**)&ctx,    g_ctx);
    cudaGetSymbolAddress((void**)&hs,     g_hs);
    cudaGetSymbolAddress((void**)&x2,     g_x2);
    cudaGetSymbolAddress((void**)&counts, g_counts);

    float *gh;
    cudaGetSymbolAddress((void**)&gh, g_h);

    cudaFuncSetAttribute(attn_kernel2, cudaFuncAttributeMaxDynamicSharedMemorySize, 71680);

    // attention sub-block
    ln_kernel<<<NTOK, 256>>>(hidden, ln1_g, ln1_b, xln1);
    mma_gemm<0><<<dim3(D3/128, NTOK/128, 1), 256>>>(xln1, w_attn, b_attn, nullptr, qkv, NTOK, D3, DD);
    attn_kernel2<<<dim3(SS/64, BB*HH), dim3(16,16), 69632>>>();
    mma_gemm<1><<<dim3(DD/128, NTOK/128, 1), 256>>>(ctx, w_attnproj, b_attnproj, hidden, hs, NTOK, DD, DD);

    // out starts as residual (hs); MoE PROJ accumulates into it
    cudaMemcpyAsync(out, hs, (size_t)NTOK*DD*sizeof(float), cudaMemcpyDeviceToDevice);

    // MoE sub-block
    ln_kernel<<<NTOK, 256>>>(hs, ln2_g, ln2_b, x2);
    cudaMemsetAsync(counts, 0, EE*sizeof(int));
    router_kernel<<<(NTOK*32)/256, 256>>>(x2, w_router);
    offsets_kernel<<<1,1>>>();
    fill_kernel<<<NTOK/256, 256>>>();
    mma_gemm<2><<<dim3(FF/128, NPAIR/128, EE), 256>>>(x2, w_fc, b_fc, nullptr, gh, NPAIR, FF, DD);
    mma_gemm<3><<<dim3(DD/128, NPAIR/128, EE), 256>>>(gh, w_proj, b_proj, nullptr, out, NPAIR, DD, FF);
}

// round 4
// speedup vs baseline: 4.0570x; 1.1584x over previous
#include <cuda_runtime.h>
#include <cuda_bf16.h>
#include <math.h>

// Problem constants
#define BB 2
#define SS 1024
#define DD 768
#define HH 12
#define HDIM 64
#define EE 8
#define TOPK 2
#define FF 3072
#define NTOK (BB*SS)        // 2048
#define D3 (3*DD)           // 2304
#define NPAIR (NTOK*TOPK)   // 4096

// ---------------- device scratch ----------------
__device__ float g_xln1[NTOK*DD];
__device__ float g_qkv [NTOK*D3];
__device__ float g_ctx [NTOK*DD];
__device__ float g_hs  [NTOK*DD];
__device__ float g_x2  [NTOK*DD];
__device__ float g_h   [NPAIR*FF];
__device__ int   g_topidx[NTOK*TOPK];
__device__ float g_topw [NTOK*TOPK];
__device__ int   g_counts[EE];
__device__ int   g_offsets[EE+1];
__device__ int   g_cursor[EE];
__device__ int   g_pairtok[NPAIR];
__device__ float g_pairw [NPAIR];

// ---------------- helpers ----------------
__device__ __forceinline__ unsigned f2tf32(float x) {
    unsigned u;
    asm("cvt.rna.tf32.f32 %0, %1;" : "=r"(u) : "f"(x));
    return u;
}
__device__ __forceinline__ void mma_tf32(float c[4], unsigned a0, unsigned a1,
                                         unsigned a2, unsigned a3,
                                         unsigned b0, unsigned b1) {
    asm volatile(
        "mma.sync.aligned.m16n8k8.row.col.f32.tf32.tf32.f32 "
        "{%0,%1,%2,%3},{%4,%5,%6,%7},{%8,%9},{%0,%1,%2,%3};"
        : "+f"(c[0]), "+f"(c[1]), "+f"(c[2]), "+f"(c[3])
        : "r"(a0), "r"(a1), "r"(a2), "r"(a3), "r"(b0), "r"(b1));
}
__device__ __forceinline__ void cp16(float* smem_dst, const float* gsrc, bool valid) {
    unsigned dst = (unsigned)__cvta_generic_to_shared(smem_dst);
    int sz = valid ? 16 : 0;
    asm volatile("cp.async.cg.shared.global [%0], [%1], 16, %2;"
                 :: "r"(dst), "l"(gsrc), "r"(sz));
}
__device__ __forceinline__ void cp_commit() {
    asm volatile("cp.async.commit_group;");
}
__device__ __forceinline__ void cp_wait0() {
    asm volatile("cp.async.wait_group 0;" ::: "memory");
}

// ---------------- LayerNorm ----------------
__global__ void ln_kernel(const float* __restrict__ x,
                          const float* __restrict__ g,
                          const float* __restrict__ b,
                          float* __restrict__ out) {
    int row = blockIdx.x;
    int tid = threadIdx.x;
    const float* xr = x + (size_t)row*DD;
    float v[3];
    float s = 0.f, s2 = 0.f;
#pragma unroll
    for (int i = 0; i < 3; i++) {
        v[i] = xr[tid + i*256];
        s += v[i]; s2 += v[i]*v[i];
    }
    __shared__ float2 red[256];
    red[tid] = make_float2(s, s2);
    __syncthreads();
    for (int off = 128; off > 0; off >>= 1) {
        if (tid < off) {
            red[tid].x += red[tid+off].x;
            red[tid].y += red[tid+off].y;
        }
        __syncthreads();
    }
    float mu  = red[0].x * (1.0f/DD);
    float var = red[0].y * (1.0f/DD) - mu*mu;
    float inv = rsqrtf(var + 1e-5f);
    float* orow = out + (size_t)row*DD;
#pragma unroll
    for (int i = 0; i < 3; i++) {
        int c = tid + i*256;
        orow[c] = (v[i] - mu) * inv * g[c] + b[c];
    }
}

// ---------------- TF32 MMA GEMM, cp.async 2-stage pipeline ----------------
// MODE 0: C = A@B + bias                        (QKV)
// MODE 1: C = A@B + bias + resid; also C2 = C   (attn out proj + residual copy)
// MODE 2: C = gelu(gather(A)@B[e] + bias[e])    (MoE FC, write g_h)
// MODE 3: atomic C[tok] += w * (A@B[e]+bias[e]) (MoE PROJ)
template<int MODE>
__global__ void __launch_bounds__(256)
mma_gemm(const float* __restrict__ A, const float* __restrict__ B,
         const float* __restrict__ bias, const float* __restrict__ resid,
         float* __restrict__ C, float* __restrict__ C2, int M, int N, int K) {
    int e = 0, seg = 0, cnt = M;
    if (MODE >= 2) {
        e = blockIdx.z;
        seg = g_offsets[e];
        cnt = g_offsets[e+1] - seg;
    }
    int rowBase = blockIdx.y * 128;
    if (rowBase >= cnt) return;
    int colBase = blockIdx.x * 128;
    const float* Bm = B + (size_t)e*K*N;
    const float* biasv = bias + (size_t)e*N;

    __shared__ float As[2][128][20];   // [stage][m][k]
    __shared__ float Bs[2][16][136];   // [stage][k][n]
    __shared__ int sTok[128];

    int tid = threadIdx.x;
    int lane = tid & 31, warp = tid >> 5;
    int wy = warp >> 2, wx = warp & 3;   // warp tile: rows wy*64, cols wx*32
    int g4 = lane >> 2, t4 = lane & 3;

    if (MODE == 2) {
        if (tid < 128)
            sTok[tid] = (rowBase + tid < cnt) ? g_pairtok[seg + rowBase + tid] : -1;
        __syncthreads();
    }

    // per-thread load coordinates (2 A chunks, 2 B chunks of 16B each)
    int ar[2], akq[2];
    const float* aptr[2];
    bool avalid[2];
#pragma unroll
    for (int l = 0; l < 2; l++) {
        int idx = tid + l*256;
        ar[l] = idx >> 2; akq[l] = (idx & 3) * 4;
        if (MODE == 2) {
            int tk = sTok[ar[l]];
            avalid[l] = (tk >= 0);
            aptr[l] = A + (avalid[l] ? (size_t)tk*K : 0) + akq[l];
        } else if (MODE == 3) {
            avalid[l] = (rowBase + ar[l] < cnt);
            aptr[l] = A + (avalid[l] ? (size_t)(seg + rowBase + ar[l])*K : 0) + akq[l];
        } else {
            avalid[l] = true;
            aptr[l] = A + (size_t)(rowBase + ar[l])*K + akq[l];
        }
    }
    int br[2], bc4[2];
    const float* bptr[2];
#pragma unroll
    for (int l = 0; l < 2; l++) {
        int idx = tid + l*256;
        br[l] = idx >> 5; bc4[l] = (idx & 31) * 4;
        bptr[l] = Bm + (size_t)br[l]*N + colBase + bc4[l];
    }

    float acc[4][4][4] = {};
    int nt = K / 16;

    // prologue: stage 0, tile 0
#pragma unroll
    for (int l = 0; l < 2; l++) cp16(&As[0][ar[l]][akq[l]], aptr[l], avalid[l]);
#pragma unroll
    for (int l = 0; l < 2; l++) cp16(&Bs[0][br[l]][bc4[l]], bptr[l], true);
    cp_commit();

    for (int kt = 0; kt < nt; kt++) {
        cp_wait0();
        __syncthreads();
        // issue next tile's loads (overlap with compute below)
        if (kt + 1 < nt) {
            int s2 = (kt + 1) & 1;
            int k0 = (kt + 1) * 16;
#pragma unroll
            for (int l = 0; l < 2; l++)
                cp16(&As[s2][ar[l]][akq[l]], aptr[l] + k0, avalid[l]);
#pragma unroll
            for (int l = 0; l < 2; l++)
                cp16(&Bs[s2][br[l]][bc4[l]], bptr[l] + (size_t)k0*N, true);
            cp_commit();
        }
        int s = kt & 1;
#pragma unroll
        for (int ks = 0; ks < 16; ks += 8) {
            unsigned af[4][4];
#pragma unroll
            for (int mi = 0; mi < 4; mi++) {
                int r = wy*64 + mi*16 + g4;
                int kc = ks + t4;
                af[mi][0] = f2tf32(As[s][r][kc]);
                af[mi][1] = f2tf32(As[s][r+8][kc]);
                af[mi][2] = f2tf32(As[s][r][kc+4]);
                af[mi][3] = f2tf32(As[s][r+8][kc+4]);
            }
            unsigned bf[4][2];
#pragma unroll
            for (int ni = 0; ni < 4; ni++) {
                int cc = wx*32 + ni*8 + g4;
                bf[ni][0] = f2tf32(Bs[s][ks + t4][cc]);
                bf[ni][1] = f2tf32(Bs[s][ks + t4 + 4][cc]);
            }
#pragma unroll
            for (int mi = 0; mi < 4; mi++)
#pragma unroll
                for (int ni = 0; ni < 4; ni++)
                    mma_tf32(acc[mi][ni], af[mi][0], af[mi][1], af[mi][2], af[mi][3],
                             bf[ni][0], bf[ni][1]);
        }
    }

    // epilogue
#pragma unroll
    for (int mi = 0; mi < 4; mi++) {
#pragma unroll
        for (int ci = 0; ci < 2; ci++) {
            int r = wy*64 + mi*16 + g4 + ci*8;
            int grow = rowBase + r;
            if (grow >= cnt) continue;
#pragma unroll
            for (int ni = 0; ni < 4; ni++) {
                int col = colBase + wx*32 + ni*8 + t4*2;
                float v0 = acc[mi][ni][ci*2 + 0];
                float v1 = acc[mi][ni][ci*2 + 1];
                if (MODE == 0) {
                    v0 += biasv[col]; v1 += biasv[col+1];
                    *(float2*)&C[(size_t)grow*N + col] = make_float2(v0, v1);
                } else if (MODE == 1) {
                    const float2 rr = *(const float2*)&resid[(size_t)grow*N + col];
                    v0 += biasv[col]   + rr.x;
                    v1 += biasv[col+1] + rr.y;
                    *(float2*)&C [(size_t)grow*N + col] = make_float2(v0, v1);
                    *(float2*)&C2[(size_t)grow*N + col] = make_float2(v0, v1);
                } else if (MODE == 2) {
                    v0 += biasv[col]; v1 += biasv[col+1];
                    v0 = 0.5f*v0*(1.0f + erff(v0*0.70710678118654752f));
                    v1 = 0.5f*v1*(1.0f + erff(v1*0.70710678118654752f));
                    *(float2*)&C[(size_t)(seg + grow)*N + col] = make_float2(v0, v1);
                } else {
                    int p = seg + grow;
                    int tok = g_pairtok[p];
                    float pw = g_pairw[p];
                    atomicAdd(&C[(size_t)tok*N + col],   pw*(v0 + biasv[col]));
                    atomicAdd(&C[(size_t)tok*N + col+1], pw*(v1 + biasv[col+1]));
                }
            }
        }
    }
}

// ---------------- Attention: block per (64-query tile, b*h) ----------------
__global__ void __launch_bounds__(256) attn_kernel2() {
    extern __shared__ float sm[];
    float* sQt = sm;            // [d*68 + r]
    float* sKt = sm + 4352;     // [d*68 + j]
    float* sV  = sm + 8704;     // [j*68 + d]
    float* sS  = sm + 13056;    // [r*68 + j]

    int tx = threadIdx.x, ty = threadIdx.y;
    int tid = ty*16 + tx;
    int qt = (gridDim.x - 1) - blockIdx.x;    // heavy tiles first
    int bh = blockIdx.y;
    int b = bh / HH, h = bh % HH;
    size_t qkvBase = (size_t)(b*SS)*D3 + h*HDIM;

#pragma unroll
    for (int l = 0; l < 4; l++) {
        int idx = tid + l*256;
        int r = idx >> 4, d4 = (idx & 15) * 4;
        float4 v = *(const float4*)&g_qkv[qkvBase + (size_t)(qt*64 + r)*D3 + d4];
        sQt[(d4+0)*68 + r] = v.x * 0.125f;
        sQt[(d4+1)*68 + r] = v.y * 0.125f;
        sQt[(d4+2)*68 + r] = v.z * 0.125f;
        sQt[(d4+3)*68 + r] = v.w * 0.125f;
    }

    float m[4], l[4], o[4][4];
#pragma unroll
    for (int i = 0; i < 4; i++) {
        m[i] = -1e30f; l[i] = 0.f;
#pragma unroll
        for (int j = 0; j < 4; j++) o[i][j] = 0.f;
    }

    for (int kt = 0; kt <= qt; kt++) {
        __syncthreads();
#pragma unroll
        for (int lq = 0; lq < 4; lq++) {
            int idx = tid + lq*256;
            int r = idx >> 4, d4 = (idx & 15) * 4;
            size_t rowp = qkvBase + (size_t)(kt*64 + r)*D3;
            float4 kv = *(const float4*)&g_qkv[rowp + DD + d4];
            sKt[(d4+0)*68 + r] = kv.x;
            sKt[(d4+1)*68 + r] = kv.y;
            sKt[(d4+2)*68 + r] = kv.z;
            sKt[(d4+3)*68 + r] = kv.w;
            float4 vv = *(const float4*)&g_qkv[rowp + 2*DD + d4];
            *(float4*)&sV[r*68 + d4] = vv;
        }
        __syncthreads();

        float s[4][4] = {};
#pragma unroll 8
        for (int d = 0; d < 64; d++) {
            float4 a4 = *(const float4*)&sQt[d*68 + ty*4];
            float4 b4 = *(const float4*)&sKt[d*68 + tx*4];
            float a[4] = {a4.x, a4.y, a4.z, a4.w};
            float bb[4] = {b4.x, b4.y, b4.z, b4.w};
#pragma unroll
            for (int i = 0; i < 4; i++)
#pragma unroll
                for (int j = 0; j < 4; j++)
                    s[i][j] += a[i]*bb[j];
        }
        if (kt == qt) {
#pragma unroll
            for (int i = 0; i < 4; i++)
#pragma unroll
                for (int j = 0; j < 4; j++)
                    if (tx*4 + j > ty*4 + i) s[i][j] = -1e30f;
        }
#pragma unroll
        for (int i = 0; i < 4; i++) {
            float rm = fmaxf(fmaxf(s[i][0], s[i][1]), fmaxf(s[i][2], s[i][3]));
#pragma unroll
            for (int off = 8; off >= 1; off >>= 1)
                rm = fmaxf(rm, __shfl_xor_sync(0xffffffffu, rm, off));
            float nm = fmaxf(m[i], rm);
            float sc = __expf(m[i] - nm);
            float p0 = __expf(s[i][0] - nm);
            float p1 = __expf(s[i][1] - nm);
            float p2 = __expf(s[i][2] - nm);
            float p3 = __expf(s[i][3] - nm);
            float ps = p0 + p1 + p2 + p3;
#pragma unroll
            for (int off = 8; off >= 1; off >>= 1)
                ps += __shfl_xor_sync(0xffffffffu, ps, off);
            l[i] = l[i]*sc + ps;
            m[i] = nm;
#pragma unroll
            for (int j = 0; j < 4; j++) o[i][j] *= sc;
            *(float4*)&sS[(ty*4+i)*68 + tx*4] = make_float4(p0, p1, p2, p3);
        }
        __syncthreads();

#pragma unroll 4
        for (int j4 = 0; j4 < 16; j4++) {
            float p[4][4];
#pragma unroll
            for (int i = 0; i < 4; i++) {
                float4 t = *(const float4*)&sS[(ty*4+i)*68 + j4*4];
                p[i][0] = t.x; p[i][1] = t.y; p[i][2] = t.z; p[i][3] = t.w;
            }
#pragma unroll
            for (int jj = 0; jj < 4; jj++) {
                float4 v4 = *(const float4*)&sV[(j4*4+jj)*68 + tx*4];
                float vv[4] = {v4.x, v4.y, v4.z, v4.w};
#pragma unroll
                for (int i = 0; i < 4; i++)
#pragma unroll
                    for (int d = 0; d < 4; d++)
                        o[i][d] += p[i][jj]*vv[d];
            }
        }
    }

#pragma unroll
    for (int i = 0; i < 4; i++) {
        float inv = 1.0f / l[i];
        float4 o4 = make_float4(o[i][0]*inv, o[i][1]*inv, o[i][2]*inv, o[i][3]*inv);
        *(float4*)&g_ctx[(size_t)(b*SS + qt*64 + ty*4 + i)*DD + h*HDIM + tx*4] = o4;
    }
}

// ---------------- Router + top-2 ----------------
__global__ void router_kernel(const float* __restrict__ x2, const float* __restrict__ w_router) {
    int gid  = blockIdx.x*blockDim.x + threadIdx.x;
    int warp = gid >> 5;
    int lane = gid & 31;
    if (warp >= NTOK) return;
    float p[EE] = {};
    const float* xr = x2 + (size_t)warp*DD;
    for (int d = lane; d < DD; d += 32) {
        float xv = xr[d];
#pragma unroll
        for (int e = 0; e < EE; e++) p[e] += xv * w_router[e*DD + d];
    }
#pragma unroll
    for (int off = 16; off > 0; off >>= 1)
#pragma unroll
        for (int e = 0; e < EE; e++)
            p[e] += __shfl_down_sync(0xffffffffu, p[e], off);
    if (lane == 0) {
        float mx = p[0];
#pragma unroll
        for (int e = 1; e < EE; e++) mx = fmaxf(mx, p[e]);
        float ex[EE];
#pragma unroll
        for (int e = 0; e < EE; e++) ex[e] = expf(p[e] - mx);
        int i0 = 0;
#pragma unroll
        for (int e = 1; e < EE; e++) if (ex[e] > ex[i0]) i0 = e;
        int i1 = (i0 == 0) ? 1 : 0;
#pragma unroll
        for (int e = 0; e < EE; e++) if (e != i0 && ex[e] > ex[i1]) i1 = e;
        float denom = ex[i0] + ex[i1];
        g_topidx[warp*2+0] = i0;  g_topw[warp*2+0] = ex[i0]/denom;
        g_topidx[warp*2+1] = i1;  g_topw[warp*2+1] = ex[i1]/denom;
        atomicAdd(&g_counts[i0], 1);
        atomicAdd(&g_counts[i1], 1);
    }
}

__global__ void offsets_kernel() {
    g_offsets[0] = 0;
    for (int e = 0; e < EE; e++) {
        g_offsets[e+1] = g_offsets[e] + g_counts[e];
        g_cursor[e] = 0;
    }
}

__global__ void fill_kernel() {
    int t = blockIdx.x*blockDim.x + threadIdx.x;
    if (t >= NTOK) return;
#pragma unroll
    for (int k = 0; k < TOPK; k++) {
        int e = g_topidx[t*2+k];
        int pos = g_offsets[e] + atomicAdd(&g_cursor[e], 1);
        g_pairtok[pos] = t;
        g_pairw[pos]   = g_topw[t*2+k];
    }
}

// ---------------- launch ----------------
extern "C" void kernel_launch(void* const* d_in, const int* in_sizes, int n_in,
                              void* d_out, int out_size) {
    const float* hidden     = (const float*)d_in[0];
    const float* ln1_g      = (const float*)d_in[1];
    const float* ln1_b      = (const float*)d_in[2];
    const float* w_attn     = (const float*)d_in[3];
    const float* b_attn     = (const float*)d_in[4];
    const float* w_attnproj = (const float*)d_in[5];
    const float* b_attnproj = (const float*)d_in[6];
    const float* ln2_g      = (const float*)d_in[7];
    const float* ln2_b      = (const float*)d_in[8];
    const float* w_router   = (const float*)d_in[9];
    const float* w_fc       = (const float*)d_in[10];
    const float* b_fc       = (const float*)d_in[11];
    const float* w_proj     = (const float*)d_in[12];
    const float* b_proj     = (const float*)d_in[13];
    float* out = (float*)d_out;

    float *xln1, *qkv, *ctx, *hs, *x2, *gh;
    int* counts;
    cudaGetSymbolAddress((void**)&xln1,   g_xln1);
    cudaGetSymbolAddress((void**)&qkv,    g_qkv);
    cudaGetSymbolAddress((void**)&ctx,    g_ctx);
    cudaGetSymbolAddress((void**)&hs,     g_hs);
    cudaGetSymbolAddress((void**)&x2,     g_x2);
    cudaGetSymbolAddress((void**)&gh,     g_h);
    cudaGetSymbolAddress((void**)&counts, g_counts);

    cudaFuncSetAttribute(attn_kernel2, cudaFuncAttributeMaxDynamicSharedMemorySize, 71680);

    // attention sub-block
    ln_kernel<<<NTOK, 256>>>(hidden, ln1_g, ln1_b, xln1);
    mma_gemm<0><<<dim3(D3/128, NTOK/128, 1), 256>>>(xln1, w_attn, b_attn, nullptr, qkv, nullptr, NTOK, D3, DD);
    attn_kernel2<<<dim3(SS/64, BB*HH), dim3(16,16), 69632>>>();
    // mode 1 writes hs AND initializes out (= hs) in one pass
    mma_gemm<1><<<dim3(DD/128, NTOK/128, 1), 256>>>(ctx, w_attnproj, b_attnproj, hidden, hs, out, NTOK, DD, DD);

    // MoE sub-block
    ln_kernel<<<NTOK, 256>>>(hs, ln2_g, ln2_b, x2);
    cudaMemsetAsync(counts, 0, EE*sizeof(int));
    router_kernel<<<(NTOK*32)/256, 256>>>(x2, w_router);
    offsets_kernel<<<1,1>>>();
    fill_kernel<<<NTOK/256, 256>>>();
    mma_gemm<2><<<dim3(FF/128, NPAIR/128, EE), 256>>>(x2, w_fc, b_fc, nullptr, gh, nullptr, NPAIR, FF, DD);
    mma_gemm<3><<<dim3(DD/128, NPAIR/128, EE), 256>>>(gh, w_proj, b_proj, nullptr, out, nullptr, NPAIR, DD, FF);
}

// round 5
// speedup vs baseline: 4.4771x; 1.1035x over previous
#include <cuda_runtime.h>
#include <cuda_bf16.h>
#include <math.h>

// Problem constants
#define BB 2
#define SS 1024
#define DD 768
#define HH 12
#define HDIM 64
#define EE 8
#define TOPK 2
#define FF 3072
#define NTOK (BB*SS)        // 2048
#define D3 (3*DD)           // 2304
#define NPAIR (NTOK*TOPK)   // 4096

// ---------------- device scratch ----------------
__device__ float g_xln1[NTOK*DD];
__device__ float g_qkv [NTOK*D3];
__device__ float g_ctx [NTOK*DD];
__device__ float g_hs  [NTOK*DD];
__device__ float g_x2  [NTOK*DD];
__device__ float g_h   [NPAIR*FF];
__device__ int   g_topidx[NTOK*TOPK];
__device__ float g_topw [NTOK*TOPK];
__device__ int   g_counts[EE];
__device__ int   g_offsets[EE+1];
__device__ int   g_cursor[EE];
__device__ int   g_pairtok[NPAIR];
__device__ float g_pairw [NPAIR];

// ---------------- helpers ----------------
__device__ __forceinline__ unsigned f2tf32(float x) {
    unsigned u;
    asm("cvt.rna.tf32.f32 %0, %1;" : "=r"(u) : "f"(x));
    return u;
}
__device__ __forceinline__ void mma_tf32(float c[4], unsigned a0, unsigned a1,
                                         unsigned a2, unsigned a3,
                                         unsigned b0, unsigned b1) {
    asm volatile(
        "mma.sync.aligned.m16n8k8.row.col.f32.tf32.tf32.f32 "
        "{%0,%1,%2,%3},{%4,%5,%6,%7},{%8,%9},{%0,%1,%2,%3};"
        : "+f"(c[0]), "+f"(c[1]), "+f"(c[2]), "+f"(c[3])
        : "r"(a0), "r"(a1), "r"(a2), "r"(a3), "r"(b0), "r"(b1));
}
__device__ __forceinline__ void cp16(float* smem_dst, const float* gsrc, bool valid) {
    unsigned dst = (unsigned)__cvta_generic_to_shared(smem_dst);
    int sz = valid ? 16 : 0;
    asm volatile("cp.async.cg.shared.global [%0], [%1], 16, %2;"
                 :: "r"(dst), "l"(gsrc), "r"(sz));
}
__device__ __forceinline__ void cp_commit() {
    asm volatile("cp.async.commit_group;");
}
__device__ __forceinline__ void cp_wait0() {
    asm volatile("cp.async.wait_group 0;" ::: "memory");
}
__device__ __forceinline__ void cp_wait1() {
    asm volatile("cp.async.wait_group 1;" ::: "memory");
}

// ---------------- LayerNorm ----------------
__global__ void ln_kernel(const float* __restrict__ x,
                          const float* __restrict__ g,
                          const float* __restrict__ b,
                          float* __restrict__ out) {
    int row = blockIdx.x;
    int tid = threadIdx.x;
    const float* xr = x + (size_t)row*DD;
    float v[3];
    float s = 0.f, s2 = 0.f;
#pragma unroll
    for (int i = 0; i < 3; i++) {
        v[i] = xr[tid + i*256];
        s += v[i]; s2 += v[i]*v[i];
    }
    __shared__ float2 red[256];
    red[tid] = make_float2(s, s2);
    __syncthreads();
    for (int off = 128; off > 0; off >>= 1) {
        if (tid < off) {
            red[tid].x += red[tid+off].x;
            red[tid].y += red[tid+off].y;
        }
        __syncthreads();
    }
    float mu  = red[0].x * (1.0f/DD);
    float var = red[0].y * (1.0f/DD) - mu*mu;
    float inv = rsqrtf(var + 1e-5f);
    float* orow = out + (size_t)row*DD;
#pragma unroll
    for (int i = 0; i < 3; i++) {
        int c = tid + i*256;
        orow[c] = (v[i] - mu) * inv * g[c] + b[c];
    }
}

// ---------------- TF32 MMA GEMM, cp.async 3-stage pipeline ----------------
// MODE 0: C = A@B + bias                        (QKV)
// MODE 1: C = A@B + bias + resid; also C2 = C   (attn out proj + residual copy)
// MODE 2: C = gelu(gather(A)@B[e] + bias[e])    (MoE FC, write g_h)
// MODE 3: atomic C[tok] += w * (A@B[e]+bias[e]) (MoE PROJ)
// TM = row-tile (128 or 64); block = 256 thr = 8 warps (2m x 4n)
template<int MODE, int TM>
__global__ void __launch_bounds__(256)
mma_gemm(const float* __restrict__ A, const float* __restrict__ B,
         const float* __restrict__ bias, const float* __restrict__ resid,
         float* __restrict__ C, float* __restrict__ C2, int M, int N, int K) {
    constexpr int MI = TM/32;        // m16 tiles per warp
    constexpr int AC = TM/64;        // A float4 chunks per thread
    constexpr int ASTRIDE = TM*20;   // floats per A stage
    constexpr int BSTRIDE = 16*136;  // floats per B stage

    int e = 0, seg = 0, cnt = M;
    if (MODE >= 2) {
        e = blockIdx.z;
        seg = g_offsets[e];
        cnt = g_offsets[e+1] - seg;
    }
    int rowBase = blockIdx.y * TM;
    if (rowBase >= cnt) return;
    int colBase = blockIdx.x * 128;
    const float* Bm = B + (size_t)e*K*N;
    const float* biasv = bias + (size_t)e*N;

    extern __shared__ float smem[];
    float* Asm = smem;                 // 3 stages of [TM][20]
    float* Bsm = smem + 3*ASTRIDE;     // 3 stages of [16][136]
    __shared__ int sTok[TM];

    int tid = threadIdx.x;
    int lane = tid & 31, warp = tid >> 5;
    int wy = warp >> 2, wx = warp & 3;
    int g4 = lane >> 2, t4 = lane & 3;

    if (MODE == 2) {
        for (int i = tid; i < TM; i += 256)
            sTok[i] = (rowBase + i < cnt) ? g_pairtok[seg + rowBase + i] : -1;
        __syncthreads();
    }

    // per-thread load coordinates
    int ar[AC], akq[AC];
    const float* aptr[AC];
    bool avalid[AC];
#pragma unroll
    for (int l = 0; l < AC; l++) {
        int idx = tid + l*256;
        ar[l] = idx >> 2; akq[l] = (idx & 3) * 4;
        if (MODE == 2) {
            int tk = sTok[ar[l]];
            avalid[l] = (tk >= 0);
            aptr[l] = A + (avalid[l] ? (size_t)tk*K : 0) + akq[l];
        } else if (MODE == 3) {
            avalid[l] = (rowBase + ar[l] < cnt);
            aptr[l] = A + (avalid[l] ? (size_t)(seg + rowBase + ar[l])*K : 0) + akq[l];
        } else {
            avalid[l] = true;
            aptr[l] = A + (size_t)(rowBase + ar[l])*K + akq[l];
        }
    }
    int br[2], bc4[2];
    const float* bptr[2];
#pragma unroll
    for (int l = 0; l < 2; l++) {
        int idx = tid + l*256;
        br[l] = idx >> 5; bc4[l] = (idx & 31) * 4;
        bptr[l] = Bm + (size_t)br[l]*N + colBase + bc4[l];
    }

    float acc[MI][4][4] = {};
    int nt = K / 16;

    // prologue: tiles 0 and 1
#pragma unroll
    for (int p = 0; p < 2; p++) {
        int k0 = p * 16;
#pragma unroll
        for (int l = 0; l < AC; l++)
            cp16(&Asm[p*ASTRIDE + ar[l]*20 + akq[l]], aptr[l] + k0, avalid[l]);
#pragma unroll
        for (int l = 0; l < 2; l++)
            cp16(&Bsm[p*BSTRIDE + br[l]*136 + bc4[l]], bptr[l] + (size_t)k0*N, true);
        cp_commit();
    }

    for (int kt = 0; kt < nt; kt++) {
        if (kt + 1 < nt) cp_wait1(); else cp_wait0();
        __syncthreads();
        if (kt + 2 < nt) {
            int st = (kt + 2) % 3;
            int k0 = (kt + 2) * 16;
#pragma unroll
            for (int l = 0; l < AC; l++)
                cp16(&Asm[st*ASTRIDE + ar[l]*20 + akq[l]], aptr[l] + k0, avalid[l]);
#pragma unroll
            for (int l = 0; l < 2; l++)
                cp16(&Bsm[st*BSTRIDE + br[l]*136 + bc4[l]], bptr[l] + (size_t)k0*N, true);
            cp_commit();
        }
        const float* As = Asm + (kt % 3)*ASTRIDE;
        const float* Bs = Bsm + (kt % 3)*BSTRIDE;
#pragma unroll
        for (int ks = 0; ks < 16; ks += 8) {
            unsigned af[MI][4];
#pragma unroll
            for (int mi = 0; mi < MI; mi++) {
                int r = wy*(TM/2) + mi*16 + g4;
                int kc = ks + t4;
                af[mi][0] = f2tf32(As[r*20 + kc]);
                af[mi][1] = f2tf32(As[(r+8)*20 + kc]);
                af[mi][2] = f2tf32(As[r*20 + kc+4]);
                af[mi][3] = f2tf32(As[(r+8)*20 + kc+4]);
            }
            unsigned bf[4][2];
#pragma unroll
            for (int ni = 0; ni < 4; ni++) {
                int cc = wx*32 + ni*8 + g4;
                bf[ni][0] = f2tf32(Bs[(ks + t4)*136 + cc]);
                bf[ni][1] = f2tf32(Bs[(ks + t4 + 4)*136 + cc]);
            }
#pragma unroll
            for (int mi = 0; mi < MI; mi++)
#pragma unroll
                for (int ni = 0; ni < 4; ni++)
                    mma_tf32(acc[mi][ni], af[mi][0], af[mi][1], af[mi][2], af[mi][3],
                             bf[ni][0], bf[ni][1]);
        }
    }

    // epilogue
#pragma unroll
    for (int mi = 0; mi < MI; mi++) {
#pragma unroll
        for (int ci = 0; ci < 2; ci++) {
            int r = wy*(TM/2) + mi*16 + g4 + ci*8;
            int grow = rowBase + r;
            if (grow >= cnt) continue;
#pragma unroll
            for (int ni = 0; ni < 4; ni++) {
                int col = colBase + wx*32 + ni*8 + t4*2;
                float v0 = acc[mi][ni][ci*2 + 0];
                float v1 = acc[mi][ni][ci*2 + 1];
                if (MODE == 0) {
                    v0 += biasv[col]; v1 += biasv[col+1];
                    *(float2*)&C[(size_t)grow*N + col] = make_float2(v0, v1);
                } else if (MODE == 1) {
                    const float2 rr = *(const float2*)&resid[(size_t)grow*N + col];
                    v0 += biasv[col]   + rr.x;
                    v1 += biasv[col+1] + rr.y;
                    *(float2*)&C [(size_t)grow*N + col] = make_float2(v0, v1);
                    *(float2*)&C2[(size_t)grow*N + col] = make_float2(v0, v1);
                } else if (MODE == 2) {
                    v0 += biasv[col]; v1 += biasv[col+1];
                    v0 = 0.5f*v0*(1.0f + erff(v0*0.70710678118654752f));
                    v1 = 0.5f*v1*(1.0f + erff(v1*0.70710678118654752f));
                    *(float2*)&C[(size_t)(seg + grow)*N + col] = make_float2(v0, v1);
                } else {
                    int p = seg + grow;
                    int tok = g_pairtok[p];
                    float pw = g_pairw[p];
                    atomicAdd(&C[(size_t)tok*N + col],   pw*(v0 + biasv[col]));
                    atomicAdd(&C[(size_t)tok*N + col+1], pw*(v1 + biasv[col+1]));
                }
            }
        }
    }
}

// ---------------- Tensor-core attention ----------------
// 128 threads = 4 warps; warp owns 16 query rows. QK^T and PV via tf32 mma.
// smem: sK[64][68] f32, sV[64][72] f32, sP[64][68] f32
#define KPAD 68
#define VPAD 72
__global__ void __launch_bounds__(128) attn_mma() {
    extern __shared__ float sm[];
    float* sK = sm;                    // 64*68
    float* sV = sm + 64*KPAD;          // 64*72
    float* sP = sV + 64*VPAD;          // 64*68

    int tid = threadIdx.x;
    int lane = tid & 31, warp = tid >> 5;
    int g4 = lane >> 2, t4 = lane & 3;
    int qt = (gridDim.x - 1) - blockIdx.x;     // heavy tiles first
    int bh = blockIdx.y;
    int b = bh / HH, h = bh % HH;
    size_t base = (size_t)(b*SS)*D3 + h*HDIM;

    int qr0 = qt*64 + warp*16 + g4;            // global query rows for this thread
    int qr1 = qr0 + 8;

    // Q fragments (scaled, tf32) cached in registers for the whole block
    unsigned aq[8][4];
#pragma unroll
    for (int ks = 0; ks < 8; ks++) {
        int d0 = ks*8 + t4;
        aq[ks][0] = f2tf32(g_qkv[base + (size_t)qr0*D3 + d0]     * 0.125f);
        aq[ks][1] = f2tf32(g_qkv[base + (size_t)qr1*D3 + d0]     * 0.125f);
        aq[ks][2] = f2tf32(g_qkv[base + (size_t)qr0*D3 + d0 + 4] * 0.125f);
        aq[ks][3] = f2tf32(g_qkv[base + (size_t)qr1*D3 + d0 + 4] * 0.125f);
    }

    float m0 = -1e30f, m1 = -1e30f, l0 = 0.f, l1 = 0.f;
    float o[8][4] = {};

    for (int kt = 0; kt <= qt; kt++) {
        __syncthreads();
        // stage K and V tiles (64 rows x 64 cols each)
#pragma unroll
        for (int l = 0; l < 8; l++) {
            int idx = tid + l*128;
            int r = idx >> 4, c4 = (idx & 15) * 4;
            size_t rowp = base + (size_t)(kt*64 + r)*D3;
            float4 kv = *(const float4*)&g_qkv[rowp + DD + c4];
            *(float4*)&sK[r*KPAD + c4] = kv;
            float4 vv = *(const float4*)&g_qkv[rowp + 2*DD + c4];
            *(float4*)&sV[r*VPAD + c4] = vv;
        }
        __syncthreads();

        // S = Q K^T : 8 j-tiles of n8
        float s[8][4] = {};
#pragma unroll
        for (int ks = 0; ks < 8; ks++) {
#pragma unroll
            for (int jt = 0; jt < 8; jt++) {
                unsigned b0 = f2tf32(sK[(jt*8 + g4)*KPAD + ks*8 + t4]);
                unsigned b1 = f2tf32(sK[(jt*8 + g4)*KPAD + ks*8 + t4 + 4]);
                mma_tf32(s[jt], aq[ks][0], aq[ks][1], aq[ks][2], aq[ks][3], b0, b1);
            }
        }
        // causal mask on diagonal tile
        if (kt == qt) {
            int lr0 = warp*16 + g4, lr1 = lr0 + 8;
#pragma unroll
            for (int jt = 0; jt < 8; jt++) {
                int c = jt*8 + t4*2;
                if (c     > lr0) s[jt][0] = -1e30f;
                if (c + 1 > lr0) s[jt][1] = -1e30f;
                if (c     > lr1) s[jt][2] = -1e30f;
                if (c + 1 > lr1) s[jt][3] = -1e30f;
            }
        }
        // online softmax (stats shared within thread-quad)
        float rm0 = -1e30f, rm1 = -1e30f;
#pragma unroll
        for (int jt = 0; jt < 8; jt++) {
            rm0 = fmaxf(rm0, fmaxf(s[jt][0], s[jt][1]));
            rm1 = fmaxf(rm1, fmaxf(s[jt][2], s[jt][3]));
        }
        rm0 = fmaxf(rm0, __shfl_xor_sync(0xffffffffu, rm0, 1));
        rm0 = fmaxf(rm0, __shfl_xor_sync(0xffffffffu, rm0, 2));
        rm1 = fmaxf(rm1, __shfl_xor_sync(0xffffffffu, rm1, 1));
        rm1 = fmaxf(rm1, __shfl_xor_sync(0xffffffffu, rm1, 2));
        float nm0 = fmaxf(m0, rm0), nm1 = fmaxf(m1, rm1);
        float sc0 = __expf(m0 - nm0), sc1 = __expf(m1 - nm1);
        float ps0 = 0.f, ps1 = 0.f;
        int pr0 = (warp*16 + g4)*KPAD, pr1 = pr0 + 8*KPAD;
#pragma unroll
        for (int jt = 0; jt < 8; jt++) {
            float p0 = __expf(s[jt][0] - nm0);
            float p1 = __expf(s[jt][1] - nm0);
            float p2 = __expf(s[jt][2] - nm1);
            float p3 = __expf(s[jt][3] - nm1);
            ps0 += p0 + p1; ps1 += p2 + p3;
            int c = jt*8 + t4*2;
            *(float2*)&sP[pr0 + c] = make_float2(p0, p1);
            *(float2*)&sP[pr1 + c] = make_float2(p2, p3);
        }
        ps0 += __shfl_xor_sync(0xffffffffu, ps0, 1);
        ps0 += __shfl_xor_sync(0xffffffffu, ps0, 2);
        ps1 += __shfl_xor_sync(0xffffffffu, ps1, 1);
        ps1 += __shfl_xor_sync(0xffffffffu, ps1, 2);
        l0 = l0*sc0 + ps0;  m0 = nm0;
        l1 = l1*sc1 + ps1;  m1 = nm1;
#pragma unroll
        for (int dt = 0; dt < 8; dt++) {
            o[dt][0] *= sc0; o[dt][1] *= sc0;
            o[dt][2] *= sc1; o[dt][3] *= sc1;
        }
        __syncwarp();   // sP rows are warp-private; warp-level visibility suffices

        // O += P V
#pragma unroll
        for (int ks = 0; ks < 8; ks++) {
            unsigned ap0 = f2tf32(sP[pr0 + ks*8 + t4]);
            unsigned ap1 = f2tf32(sP[pr1 + ks*8 + t4]);
            unsigned ap2 = f2tf32(sP[pr0 + ks*8 + t4 + 4]);
            unsigned ap3 = f2tf32(sP[pr1 + ks*8 + t4 + 4]);
#pragma unroll
            for (int dt = 0; dt < 8; dt++) {
                unsigned b0 = f2tf32(sV[(ks*8 + t4)*VPAD + dt*8 + g4]);
                unsigned b1 = f2tf32(sV[(ks*8 + t4 + 4)*VPAD + dt*8 + g4]);
                mma_tf32(o[dt], ap0, ap1, ap2, ap3, b0, b1);
            }
        }
    }

    // write ctx
    float inv0 = 1.0f / l0, inv1 = 1.0f / l1;
#pragma unroll
    for (int dt = 0; dt < 8; dt++) {
        int col = h*HDIM + dt*8 + t4*2;
        *(float2*)&g_ctx[(size_t)(b*SS + qr0)*DD + col] = make_float2(o[dt][0]*inv0, o[dt][1]*inv0);
        *(float2*)&g_ctx[(size_t)(b*SS + qr1)*DD + col] = make_float2(o[dt][2]*inv1, o[dt][3]*inv1);
    }
}

// ---------------- Router + top-2 ----------------
__global__ void router_kernel(const float* __restrict__ x2, const float* __restrict__ w_router) {
    int gid  = blockIdx.x*blockDim.x + threadIdx.x;
    int warp = gid >> 5;
    int lane = gid & 31;
    if (warp >= NTOK) return;
    float p[EE] = {};
    const float* xr = x2 + (size_t)warp*DD;
    for (int d = lane; d < DD; d += 32) {
        float xv = xr[d];
#pragma unroll
        for (int e = 0; e < EE; e++) p[e] += xv * w_router[e*DD + d];
    }
#pragma unroll
    for (int off = 16; off > 0; off >>= 1)
#pragma unroll
        for (int e = 0; e < EE; e++)
            p[e] += __shfl_down_sync(0xffffffffu, p[e], off);
    if (lane == 0) {
        float mx = p[0];
#pragma unroll
        for (int e = 1; e < EE; e++) mx = fmaxf(mx, p[e]);
        float ex[EE];
#pragma unroll
        for (int e = 0; e < EE; e++) ex[e] = expf(p[e] - mx);
        int i0 = 0;
#pragma unroll
        for (int e = 1; e < EE; e++) if (ex[e] > ex[i0]) i0 = e;
        int i1 = (i0 == 0) ? 1 : 0;
#pragma unroll
        for (int e = 0; e < EE; e++) if (e != i0 && ex[e] > ex[i1]) i1 = e;
        float denom = ex[i0] + ex[i1];
        g_topidx[warp*2+0] = i0;  g_topw[warp*2+0] = ex[i0]/denom;
        g_topidx[warp*2+1] = i1;  g_topw[warp*2+1] = ex[i1]/denom;
        atomicAdd(&g_counts[i0], 1);
        atomicAdd(&g_counts[i1], 1);
    }
}

__global__ void offsets_kernel() {
    g_offsets[0] = 0;
    for (int e = 0; e < EE; e++) {
        g_offsets[e+1] = g_offsets[e] + g_counts[e];
        g_cursor[e] = 0;
    }
}

__global__ void fill_kernel() {
    int t = blockIdx.x*blockDim.x + threadIdx.x;
    if (t >= NTOK) return;
#pragma unroll
    for (int k = 0; k < TOPK; k++) {
        int e = g_topidx[t*2+k];
        int pos = g_offsets[e] + atomicAdd(&g_cursor[e], 1);
        g_pairtok[pos] = t;
        g_pairw[pos]   = g_topw[t*2+k];
    }
}

// ---------------- launch ----------------
extern "C" void kernel_launch(void* const* d_in, const int* in_sizes, int n_in,
                              void* d_out, int out_size) {
    const float* hidden     = (const float*)d_in[0];
    const float* ln1_g      = (const float*)d_in[1];
    const float* ln1_b      = (const float*)d_in[2];
    const float* w_attn     = (const float*)d_in[3];
    const float* b_attn     = (const float*)d_in[4];
    const float* w_attnproj = (const float*)d_in[5];
    const float* b_attnproj = (const float*)d_in[6];
    const float* ln2_g      = (const float*)d_in[7];
    const float* ln2_b      = (const float*)d_in[8];
    const float* w_router   = (const float*)d_in[9];
    const float* w_fc       = (const float*)d_in[10];
    const float* b_fc       = (const float*)d_in[11];
    const float* w_proj     = (const float*)d_in[12];
    const float* b_proj     = (const float*)d_in[13];
    float* out = (float*)d_out;

    float *xln1, *qkv, *ctx, *hs, *x2, *gh;
    int* counts;
    cudaGetSymbolAddress((void**)&xln1,   g_xln1);
    cudaGetSymbolAddress((void**)&qkv,    g_qkv);
    cudaGetSymbolAddress((void**)&ctx,    g_ctx);
    cudaGetSymbolAddress((void**)&hs,     g_hs);
    cudaGetSymbolAddress((void**)&x2,     g_x2);
    cudaGetSymbolAddress((void**)&gh,     g_h);
    cudaGetSymbolAddress((void**)&counts, g_counts);

    const int SM128 = 3*(128*20 + 16*136)*4;   // 56832
    const int SM64  = 3*(64*20  + 16*136)*4;   // 41472
    const int SMATT = (64*KPAD + 64*VPAD + 64*KPAD)*4;  // 53248

    cudaFuncSetAttribute((const void*)mma_gemm<0,128>, cudaFuncAttributeMaxDynamicSharedMemorySize, SM128);
    cudaFuncSetAttribute((const void*)mma_gemm<1,64>,  cudaFuncAttributeMaxDynamicSharedMemorySize, SM64);
    cudaFuncSetAttribute((const void*)mma_gemm<2,128>, cudaFuncAttributeMaxDynamicSharedMemorySize, SM128);
    cudaFuncSetAttribute((const void*)mma_gemm<3,64>,  cudaFuncAttributeMaxDynamicSharedMemorySize, SM64);
    cudaFuncSetAttribute((const void*)attn_mma,        cudaFuncAttributeMaxDynamicSharedMemorySize, SMATT);

    // attention sub-block
    ln_kernel<<<NTOK, 256>>>(hidden, ln1_g, ln1_b, xln1);
    mma_gemm<0,128><<<dim3(D3/128, NTOK/128, 1), 256, SM128>>>(xln1, w_attn, b_attn, nullptr, qkv, nullptr, NTOK, D3, DD);
    attn_mma<<<dim3(SS/64, BB*HH), 128, SMATT>>>();
    mma_gemm<1,64><<<dim3(DD/128, NTOK/64, 1), 256, SM64>>>(ctx, w_attnproj, b_attnproj, hidden, hs, out, NTOK, DD, DD);

    // MoE sub-block
    ln_kernel<<<NTOK, 256>>>(hs, ln2_g, ln2_b, x2);
    cudaMemsetAsync(counts, 0, EE*sizeof(int));
    router_kernel<<<(NTOK*32)/256, 256>>>(x2, w_router);
    offsets_kernel<<<1,1>>>();
    fill_kernel<<<NTOK/256, 256>>>();
    mma_gemm<2,128><<<dim3(FF/128, NPAIR/128, EE), 256, SM128>>>(x2, w_fc, b_fc, nullptr, gh, nullptr, NPAIR, FF, DD);
    mma_gemm<3,64><<<dim3(DD/128, NPAIR/64, EE), 256, SM64>>>(gh, w_proj, b_proj, nullptr, out, nullptr, NPAIR, DD, FF);
}

// round 6
// speedup vs baseline: 5.7210x; 1.2778x over previous
#include <cuda_runtime.h>
#include <cuda_bf16.h>
#include <math.h>

// Problem constants
#define BB 2
#define SS 1024
#define DD 768
#define HH 12
#define HDIM 64
#define EE 8
#define TOPK 2
#define FF 3072
#define NTOK (BB*SS)        // 2048
#define D3 (3*DD)           // 2304
#define NPAIR (NTOK*TOPK)   // 4096

// ---------------- device scratch ----------------
__device__ __nv_bfloat16 g_xln1b[NTOK*DD];
__device__ __nv_bfloat16 g_qkvb [NTOK*D3];
__device__ __nv_bfloat16 g_ctxb [NTOK*DD];
__device__ float         g_hs   [NTOK*DD];
__device__ float         g_x2   [NTOK*DD];
__device__ __nv_bfloat16 g_x2b  [NTOK*DD];
__device__ __nv_bfloat16 g_hb   [NPAIR*FF];
__device__ int   g_topidx[NTOK*TOPK];
__device__ float g_topw [NTOK*TOPK];
__device__ int   g_counts[EE];
__device__ int   g_offsets[EE+1];
__device__ int   g_cursor[EE];
__device__ int   g_pairtok[NPAIR];
__device__ float g_pairw [NPAIR];

// ---------------- helpers ----------------
__device__ __forceinline__ unsigned packbf(float x, float y) {
    __nv_bfloat162 h = __floats2bfloat162_rn(x, y);
    return *(unsigned*)&h;
}
__device__ __forceinline__ void mma_bf16(float c[4], unsigned a0, unsigned a1,
                                         unsigned a2, unsigned a3,
                                         unsigned b0, unsigned b1) {
    asm volatile(
        "mma.sync.aligned.m16n8k16.row.col.f32.bf16.bf16.f32 "
        "{%0,%1,%2,%3},{%4,%5,%6,%7},{%8,%9},{%0,%1,%2,%3};"
        : "+f"(c[0]), "+f"(c[1]), "+f"(c[2]), "+f"(c[3])
        : "r"(a0), "r"(a1), "r"(a2), "r"(a3), "r"(b0), "r"(b1));
}
__device__ __forceinline__ void cp16(void* smem_dst, const void* gsrc, bool valid) {
    unsigned dst = (unsigned)__cvta_generic_to_shared(smem_dst);
    int sz = valid ? 16 : 0;
    asm volatile("cp.async.cg.shared.global [%0], [%1], 16, %2;"
                 :: "r"(dst), "l"(gsrc), "r"(sz));
}
__device__ __forceinline__ void cp_commit() {
    asm volatile("cp.async.commit_group;");
}
__device__ __forceinline__ void cp_wait0() {
    asm volatile("cp.async.wait_group 0;" ::: "memory");
}
__device__ __forceinline__ void cp_wait1() {
    asm volatile("cp.async.wait_group 1;" ::: "memory");
}

// ---------------- LayerNorm (fp32 in; optional fp32 out + bf16 out) ----------------
__global__ void ln_kernel(const float* __restrict__ x,
                          const float* __restrict__ g,
                          const float* __restrict__ b,
                          float* __restrict__ outf,
                          __nv_bfloat16* __restrict__ outb) {
    int row = blockIdx.x;
    int tid = threadIdx.x;
    const float* xr = x + (size_t)row*DD;
    float v[3];
    float s = 0.f, s2 = 0.f;
#pragma unroll
    for (int i = 0; i < 3; i++) {
        v[i] = xr[tid + i*256];
        s += v[i]; s2 += v[i]*v[i];
    }
    __shared__ float2 red[256];
    red[tid] = make_float2(s, s2);
    __syncthreads();
    for (int off = 128; off > 0; off >>= 1) {
        if (tid < off) {
            red[tid].x += red[tid+off].x;
            red[tid].y += red[tid+off].y;
        }
        __syncthreads();
    }
    float mu  = red[0].x * (1.0f/DD);
    float var = red[0].y * (1.0f/DD) - mu*mu;
    float inv = rsqrtf(var + 1e-5f);
#pragma unroll
    for (int i = 0; i < 3; i++) {
        int c = tid + i*256;
        float val = (v[i] - mu) * inv * g[c] + b[c];
        if (outf) outf[(size_t)row*DD + c] = val;
        outb[(size_t)row*DD + c] = __float2bfloat16(val);
    }
}

// ---------------- bf16 MMA GEMM, cp.async 3-stage pipeline ----------------
// A is bf16 global; B is fp32 global (cvt to bf16 at frag load).
// MODE 0: Cb = bf16(A@B + bias)                  (QKV)
// MODE 1: C = A@B + bias + resid; C2 = C (fp32)  (attn out proj + out init)
// MODE 2: Cb = bf16(gelu(gather(A)@B[e]+bias))   (MoE FC)
// MODE 3: atomic C[tok] += w*(A@B[e]+bias[e])    (MoE PROJ)
template<int MODE, int TM>
__global__ void __launch_bounds__(256)
mma_gemm(const __nv_bfloat16* __restrict__ A, const float* __restrict__ B,
         const float* __restrict__ bias, const float* __restrict__ resid,
         void* __restrict__ Cv, float* __restrict__ C2, int M, int N, int K) {
    constexpr int MI = TM/32;          // m16 tiles per warp
    constexpr int ACN = TM*2;          // 16B A chunks per stage
    constexpr int ASTRIDE = TM*24;     // bf16 elems per A stage (row pad 24)
    constexpr int BSTRIDE = 16*132;    // floats per B stage (row pad 132)

    int e = 0, seg = 0, cnt = M;
    if (MODE >= 2) {
        e = blockIdx.z;
        seg = g_offsets[e];
        cnt = g_offsets[e+1] - seg;
    }
    int rowBase = blockIdx.y * TM;
    if (rowBase >= cnt) return;
    int colBase = blockIdx.x * 128;
    const float* Bm = B + (size_t)e*K*N;
    const float* biasv = bias + (size_t)e*N;

    extern __shared__ char smembuf[];
    __nv_bfloat16* Asm = (__nv_bfloat16*)smembuf;            // 3 stages
    float* Bsm = (float*)(smembuf + 3*ASTRIDE*2);            // 3 stages
    __shared__ int sTok[TM];

    int tid = threadIdx.x;
    int lane = tid & 31, warp = tid >> 5;
    int wy = warp >> 2, wx = warp & 3;
    int g4 = lane >> 2, t4 = lane & 3;

    if (MODE == 2) {
        for (int i = tid; i < TM; i += 256)
            sTok[i] = (rowBase + i < cnt) ? g_pairtok[seg + rowBase + i] : -1;
        __syncthreads();
    }

    // per-thread A load coords: chunk idx -> (row, 8-elem half)
    int arow = tid >> 1, akh = (tid & 1) * 8;
    bool aact = (tid < ACN);
    const __nv_bfloat16* aptr = A;
    bool avalid = false;
    if (aact) {
        if (MODE == 2) {
            int tk = sTok[arow];
            avalid = (tk >= 0);
            aptr = A + (avalid ? (size_t)tk*K : 0) + akh;
        } else if (MODE == 3) {
            avalid = (rowBase + arow < cnt);
            aptr = A + (avalid ? (size_t)(seg + rowBase + arow)*K : 0) + akh;
        } else {
            avalid = true;
            aptr = A + (size_t)(rowBase + arow)*K + akh;
        }
    }
    // B: 512 chunks, 2 per thread
    int br[2], bc4[2];
    const float* bptr[2];
#pragma unroll
    for (int l = 0; l < 2; l++) {
        int idx = tid + l*256;
        br[l] = idx >> 5; bc4[l] = (idx & 31) * 4;
        bptr[l] = Bm + (size_t)br[l]*N + colBase + bc4[l];
    }

    float acc[MI][4][4] = {};
    int nt = K / 16;

    // prologue: tiles 0 and 1
#pragma unroll
    for (int p = 0; p < 2; p++) {
        int k0 = p * 16;
        if (aact) cp16(&Asm[p*ASTRIDE + arow*24 + akh], aptr + k0, avalid);
#pragma unroll
        for (int l = 0; l < 2; l++)
            cp16(&Bsm[p*BSTRIDE + br[l]*132 + bc4[l]], bptr[l] + (size_t)k0*N, true);
        cp_commit();
    }

    for (int kt = 0; kt < nt; kt++) {
        if (kt + 1 < nt) cp_wait1(); else cp_wait0();
        __syncthreads();
        if (kt + 2 < nt) {
            int st = (kt + 2) % 3;
            int k0 = (kt + 2) * 16;
            if (aact) cp16(&Asm[st*ASTRIDE + arow*24 + akh], aptr + k0, avalid);
#pragma unroll
            for (int l = 0; l < 2; l++)
                cp16(&Bsm[st*BSTRIDE + br[l]*132 + bc4[l]], bptr[l] + (size_t)k0*N, true);
            cp_commit();
        }
        const unsigned* Asw = (const unsigned*)(Asm + (kt % 3)*ASTRIDE);  // 12 words/row
        const float* Bs = Bsm + (kt % 3)*BSTRIDE;

        unsigned af[MI][4];
#pragma unroll
        for (int mi = 0; mi < MI; mi++) {
            int r = wy*(TM/2) + mi*16 + g4;
            af[mi][0] = Asw[r*12 + t4];
            af[mi][1] = Asw[(r+8)*12 + t4];
            af[mi][2] = Asw[r*12 + t4 + 4];
            af[mi][3] = Asw[(r+8)*12 + t4 + 4];
        }
        unsigned bf[4][2];
#pragma unroll
        for (int ni = 0; ni < 4; ni++) {
            int cc = wx*32 + ni*8 + g4;
            bf[ni][0] = packbf(Bs[(2*t4)*132 + cc],   Bs[(2*t4+1)*132 + cc]);
            bf[ni][1] = packbf(Bs[(2*t4+8)*132 + cc], Bs[(2*t4+9)*132 + cc]);
        }
#pragma unroll
        for (int mi = 0; mi < MI; mi++)
#pragma unroll
            for (int ni = 0; ni < 4; ni++)
                mma_bf16(acc[mi][ni], af[mi][0], af[mi][1], af[mi][2], af[mi][3],
                         bf[ni][0], bf[ni][1]);
    }

    // epilogue
    __nv_bfloat16* Cb = (__nv_bfloat16*)Cv;
    float* C = (float*)Cv;
#pragma unroll
    for (int mi = 0; mi < MI; mi++) {
#pragma unroll
        for (int ci = 0; ci < 2; ci++) {
            int r = wy*(TM/2) + mi*16 + g4 + ci*8;
            int grow = rowBase + r;
            if (grow >= cnt) continue;
#pragma unroll
            for (int ni = 0; ni < 4; ni++) {
                int col = colBase + wx*32 + ni*8 + t4*2;
                float v0 = acc[mi][ni][ci*2 + 0];
                float v1 = acc[mi][ni][ci*2 + 1];
                if (MODE == 0) {
                    v0 += biasv[col]; v1 += biasv[col+1];
                    *(__nv_bfloat162*)&Cb[(size_t)grow*N + col] = __floats2bfloat162_rn(v0, v1);
                } else if (MODE == 1) {
                    const float2 rr = *(const float2*)&resid[(size_t)grow*N + col];
                    v0 += biasv[col]   + rr.x;
                    v1 += biasv[col+1] + rr.y;
                    *(float2*)&C [(size_t)grow*N + col] = make_float2(v0, v1);
                    *(float2*)&C2[(size_t)grow*N + col] = make_float2(v0, v1);
                } else if (MODE == 2) {
                    v0 += biasv[col]; v1 += biasv[col+1];
                    v0 = 0.5f*v0*(1.0f + erff(v0*0.70710678118654752f));
                    v1 = 0.5f*v1*(1.0f + erff(v1*0.70710678118654752f));
                    *(__nv_bfloat162*)&Cb[(size_t)(seg + grow)*N + col] = __floats2bfloat162_rn(v0, v1);
                } else {
                    int p = seg + grow;
                    int tok = g_pairtok[p];
                    float pw = g_pairw[p];
                    atomicAdd(&C[(size_t)tok*N + col],   pw*(v0 + biasv[col]));
                    atomicAdd(&C[(size_t)tok*N + col+1], pw*(v1 + biasv[col+1]));
                }
            }
        }
    }
}

// ---------------- bf16 tensor-core attention ----------------
// 128 threads = 4 warps; warp owns 16 query rows. smem K/V/P tiles [64][72] bf16.
__global__ void __launch_bounds__(128) attn_mma() {
    extern __shared__ __nv_bfloat16 sm16[];
    __nv_bfloat16* sK = sm16;             // [64][72]
    __nv_bfloat16* sV = sm16 + 64*72;     // [64][72]
    __nv_bfloat16* sP = sm16 + 2*64*72;   // [64][72]
    const unsigned* sKw = (const unsigned*)sK;
    const unsigned* sPw = (const unsigned*)sP;
    const unsigned short* sVh = (const unsigned short*)sV;

    int tid = threadIdx.x;
    int lane = tid & 31, warp = tid >> 5;
    int g4 = lane >> 2, t4 = lane & 3;
    int qt = (gridDim.x - 1) - blockIdx.x;     // heavy tiles first
    int bh = blockIdx.y;
    int b = bh / HH, h = bh % HH;
    size_t base = (size_t)(b*SS)*D3 + h*HDIM;

    int qr0 = qt*64 + warp*16 + g4;
    int qr1 = qr0 + 8;

    // Q fragments (bf16, unscaled; 1/8 folded into logits)
    unsigned aq[4][4];
    const __nv_bfloat16* Qr0 = g_qkvb + base + (size_t)qr0*D3;
    const __nv_bfloat16* Qr1 = g_qkvb + base + (size_t)qr1*D3;
#pragma unroll
    for (int kb = 0; kb < 4; kb++) {
        aq[kb][0] = *(const unsigned*)&Qr0[kb*16 + 2*t4];
        aq[kb][1] = *(const unsigned*)&Qr1[kb*16 + 2*t4];
        aq[kb][2] = *(const unsigned*)&Qr0[kb*16 + 2*t4 + 8];
        aq[kb][3] = *(const unsigned*)&Qr1[kb*16 + 2*t4 + 8];
    }

    float m0 = -1e30f, m1 = -1e30f, l0 = 0.f, l1 = 0.f;
    float o[8][4] = {};
    int r0w = warp*16 + g4;      // local P row

    for (int kt = 0; kt <= qt; kt++) {
        __syncthreads();
#pragma unroll
        for (int l = 0; l < 4; l++) {
            int idx = tid + l*128;
            int r = idx >> 3, c8 = (idx & 7) * 8;
            size_t rowp = base + (size_t)(kt*64 + r)*D3;
            *(uint4*)&sK[r*72 + c8] = *(const uint4*)&g_qkvb[rowp + DD + c8];
            *(uint4*)&sV[r*72 + c8] = *(const uint4*)&g_qkvb[rowp + 2*DD + c8];
        }
        __syncthreads();

        // S = Q K^T
        float s[8][4] = {};
#pragma unroll
        for (int kb = 0; kb < 4; kb++) {
#pragma unroll
            for (int jt = 0; jt < 8; jt++) {
                unsigned b0 = sKw[(jt*8 + g4)*36 + kb*8 + t4];
                unsigned b1 = sKw[(jt*8 + g4)*36 + kb*8 + t4 + 4];
                mma_bf16(s[jt], aq[kb][0], aq[kb][1], aq[kb][2], aq[kb][3], b0, b1);
            }
        }
#pragma unroll
        for (int jt = 0; jt < 8; jt++)
#pragma unroll
            for (int c = 0; c < 4; c++) s[jt][c] *= 0.125f;

        if (kt == qt) {
            int lr0 = warp*16 + g4, lr1 = lr0 + 8;
#pragma unroll
            for (int jt = 0; jt < 8; jt++) {
                int c = jt*8 + t4*2;
                if (c     > lr0) s[jt][0] = -1e30f;
                if (c + 1 > lr0) s[jt][1] = -1e30f;
                if (c     > lr1) s[jt][2] = -1e30f;
                if (c + 1 > lr1) s[jt][3] = -1e30f;
            }
        }
        // online softmax (stats across thread-quad)
        float rm0 = -1e30f, rm1 = -1e30f;
#pragma unroll
        for (int jt = 0; jt < 8; jt++) {
            rm0 = fmaxf(rm0, fmaxf(s[jt][0], s[jt][1]));
            rm1 = fmaxf(rm1, fmaxf(s[jt][2], s[jt][3]));
        }
        rm0 = fmaxf(rm0, __shfl_xor_sync(0xffffffffu, rm0, 1));
        rm0 = fmaxf(rm0, __shfl_xor_sync(0xffffffffu, rm0, 2));
        rm1 = fmaxf(rm1, __shfl_xor_sync(0xffffffffu, rm1, 1));
        rm1 = fmaxf(rm1, __shfl_xor_sync(0xffffffffu, rm1, 2));
        float nm0 = fmaxf(m0, rm0), nm1 = fmaxf(m1, rm1);
        float sc0 = __expf(m0 - nm0), sc1 = __expf(m1 - nm1);
        float ps0 = 0.f, ps1 = 0.f;
#pragma unroll
        for (int jt = 0; jt < 8; jt++) {
            float p0 = __expf(s[jt][0] - nm0);
            float p1 = __expf(s[jt][1] - nm0);
            float p2 = __expf(s[jt][2] - nm1);
            float p3 = __expf(s[jt][3] - nm1);
            ps0 += p0 + p1; ps1 += p2 + p3;
            ((__nv_bfloat162*)sP)[r0w*36     + jt*4 + t4] = __floats2bfloat162_rn(p0, p1);
            ((__nv_bfloat162*)sP)[(r0w+8)*36 + jt*4 + t4] = __floats2bfloat162_rn(p2, p3);
        }
        ps0 += __shfl_xor_sync(0xffffffffu, ps0, 1);
        ps0 += __shfl_xor_sync(0xffffffffu, ps0, 2);
        ps1 += __shfl_xor_sync(0xffffffffu, ps1, 1);
        ps1 += __shfl_xor_sync(0xffffffffu, ps1, 2);
        l0 = l0*sc0 + ps0;  m0 = nm0;
        l1 = l1*sc1 + ps1;  m1 = nm1;
#pragma unroll
        for (int dt = 0; dt < 8; dt++) {
            o[dt][0] *= sc0; o[dt][1] *= sc0;
            o[dt][2] *= sc1; o[dt][3] *= sc1;
        }
        __syncwarp();   // sP rows are warp-private

        // O += P V
#pragma unroll
        for (int kb = 0; kb < 4; kb++) {
            unsigned ap0 = sPw[r0w*36     + kb*8 + t4];
            unsigned ap1 = sPw[(r0w+8)*36 + kb*8 + t4];
            unsigned ap2 = sPw[r0w*36     + kb*8 + t4 + 4];
            unsigned ap3 = sPw[(r0w+8)*36 + kb*8 + t4 + 4];
            int krow = kb*16 + 2*t4;
#pragma unroll
            for (int dt = 0; dt < 8; dt++) {
                int dcol = dt*8 + g4;
                unsigned b0 = (unsigned)sVh[krow*72 + dcol]
                            | ((unsigned)sVh[(krow+1)*72 + dcol] << 16);
                unsigned b1 = (unsigned)sVh[(krow+8)*72 + dcol]
                            | ((unsigned)sVh[(krow+9)*72 + dcol] << 16);
                mma_bf16(o[dt], ap0, ap1, ap2, ap3, b0, b1);
            }
        }
    }

    // write ctx (bf16)
    float inv0 = 1.0f / l0, inv1 = 1.0f / l1;
#pragma unroll
    for (int dt = 0; dt < 8; dt++) {
        int col = h*HDIM + dt*8 + t4*2;
        *(__nv_bfloat162*)&g_ctxb[(size_t)(b*SS + qr0)*DD + col] =
            __floats2bfloat162_rn(o[dt][0]*inv0, o[dt][1]*inv0);
        *(__nv_bfloat162*)&g_ctxb[(size_t)(b*SS + qr1)*DD + col] =
            __floats2bfloat162_rn(o[dt][2]*inv1, o[dt][3]*inv1);
    }
}

// ---------------- Router + top-2 (fp32 x2) ----------------
__global__ void router_kernel(const float* __restrict__ x2, const float* __restrict__ w_router) {
    int gid  = blockIdx.x*blockDim.x + threadIdx.x;
    int warp = gid >> 5;
    int lane = gid & 31;
    if (warp >= NTOK) return;
    float p[EE] = {};
    const float* xr = x2 + (size_t)warp*DD;
    for (int d = lane; d < DD; d += 32) {
        float xv = xr[d];
#pragma unroll
        for (int e = 0; e < EE; e++) p[e] += xv * w_router[e*DD + d];
    }
#pragma unroll
    for (int off = 16; off > 0; off >>= 1)
#pragma unroll
        for (int e = 0; e < EE; e++)
            p[e] += __shfl_down_sync(0xffffffffu, p[e], off);
    if (lane == 0) {
        float mx = p[0];
#pragma unroll
        for (int e = 1; e < EE; e++) mx = fmaxf(mx, p[e]);
        float ex[EE];
#pragma unroll
        for (int e = 0; e < EE; e++) ex[e] = expf(p[e] - mx);
        int i0 = 0;
#pragma unroll
        for (int e = 1; e < EE; e++) if (ex[e] > ex[i0]) i0 = e;
        int i1 = (i0 == 0) ? 1 : 0;
#pragma unroll
        for (int e = 0; e < EE; e++) if (e != i0 && ex[e] > ex[i1]) i1 = e;
        float denom = ex[i0] + ex[i1];
        g_topidx[warp*2+0] = i0;  g_topw[warp*2+0] = ex[i0]/denom;
        g_topidx[warp*2+1] = i1;  g_topw[warp*2+1] = ex[i1]/denom;
        atomicAdd(&g_counts[i0], 1);
        atomicAdd(&g_counts[i1], 1);
    }
}

__global__ void offsets_kernel() {
    g_offsets[0] = 0;
    for (int e = 0; e < EE; e++) {
        g_offsets[e+1] = g_offsets[e] + g_counts[e];
        g_cursor[e] = 0;
    }
}

__global__ void fill_kernel() {
    int t = blockIdx.x*blockDim.x + threadIdx.x;
    if (t >= NTOK) return;
#pragma unroll
    for (int k = 0; k < TOPK; k++) {
        int e = g_topidx[t*2+k];
        int pos = g_offsets[e] + atomicAdd(&g_cursor[e], 1);
        g_pairtok[pos] = t;
        g_pairw[pos]   = g_topw[t*2+k];
    }
}

// ---------------- launch ----------------
extern "C" void kernel_launch(void* const* d_in, const int* in_sizes, int n_in,
                              void* d_out, int out_size) {
    const float* hidden     = (const float*)d_in[0];
    const float* ln1_g      = (const float*)d_in[1];
    const float* ln1_b      = (const float*)d_in[2];
    const float* w_attn     = (const float*)d_in[3];
    const float* b_attn     = (const float*)d_in[4];
    const float* w_attnproj = (const float*)d_in[5];
    const float* b_attnproj = (const float*)d_in[6];
    const float* ln2_g      = (const float*)d_in[7];
    const float* ln2_b      = (const float*)d_in[8];
    const float* w_router   = (const float*)d_in[9];
    const float* w_fc       = (const float*)d_in[10];
    const float* b_fc       = (const float*)d_in[11];
    const float* w_proj     = (const float*)d_in[12];
    const float* b_proj     = (const float*)d_in[13];
    float* out = (float*)d_out;

    __nv_bfloat16 *xln1b, *qkvb, *ctxb, *x2b, *ghb;
    float *hs, *x2;
    int* counts;
    cudaGetSymbolAddress((void**)&xln1b,  g_xln1b);
    cudaGetSymbolAddress((void**)&qkvb,   g_qkvb);
    cudaGetSymbolAddress((void**)&ctxb,   g_ctxb);
    cudaGetSymbolAddress((void**)&hs,     g_hs);
    cudaGetSymbolAddress((void**)&x2,     g_x2);
    cudaGetSymbolAddress((void**)&x2b,    g_x2b);
    cudaGetSymbolAddress((void**)&ghb,    g_hb);
    cudaGetSymbolAddress((void**)&counts, g_counts);

    const int SM128 = 3*(128*24*2 + 16*132*4);  // 43776
    const int SM32  = 3*(32*24*2  + 16*132*4);  // 29952
    const int SMATT = 3*64*72*2;                // 27648

    // attention sub-block
    ln_kernel<<<NTOK, 256>>>(hidden, ln1_g, ln1_b, nullptr, xln1b);
    mma_gemm<0,128><<<dim3(D3/128, NTOK/128, 1), 256, SM128>>>(
        xln1b, w_attn, b_attn, nullptr, qkvb, nullptr, NTOK, D3, DD);
    attn_mma<<<dim3(SS/64, BB*HH), 128, SMATT>>>();
    mma_gemm<1,32><<<dim3(DD/128, NTOK/32, 1), 256, SM32>>>(
        ctxb, w_attnproj, b_attnproj, hidden, hs, out, NTOK, DD, DD);

    // MoE sub-block
    ln_kernel<<<NTOK, 256>>>(hs, ln2_g, ln2_b, x2, x2b);
    cudaMemsetAsync(counts, 0, EE*sizeof(int));
    router_kernel<<<(NTOK*32)/256, 256>>>(x2, w_router);
    offsets_kernel<<<1,1>>>();
    fill_kernel<<<NTOK/256, 256>>>();
    mma_gemm<2,128><<<dim3(FF/128, NPAIR/128, EE), 256, SM128>>>(
        x2b, w_fc, b_fc, nullptr, ghb, nullptr, NPAIR, FF, DD);
    mma_gemm<3,32><<<dim3(DD/128, NPAIR/32, EE), 256, SM32>>>(
        ghb, w_proj, b_proj, nullptr, out, nullptr, NPAIR, DD, FF);
}

// round 7
// speedup vs baseline: 7.1552x; 1.2507x over previous
#include <cuda_runtime.h>
#include <cuda_bf16.h>
#include <math.h>

// Problem constants
#define BB 2
#define SS 1024
#define DD 768
#define HH 12
#define HDIM 64
#define EE 8
#define TOPK 2
#define FF 3072
#define NTOK (BB*SS)        // 2048
#define D3 (3*DD)           // 2304
#define NPAIR (NTOK*TOPK)   // 4096

// ---------------- device scratch ----------------
__device__ __nv_bfloat16 g_xln1b[NTOK*DD];
__device__ __nv_bfloat16 g_qkvb [NTOK*D3];
__device__ __nv_bfloat16 g_ctxb [NTOK*DD];
__device__ float         g_hs   [NTOK*DD];
__device__ float         g_x2   [NTOK*DD];
__device__ __nv_bfloat16 g_x2b  [NTOK*DD];
__device__ __nv_bfloat16 g_hb   [NPAIR*FF];
// bf16 weight caches (converted once per launch)
__device__ __nv_bfloat16 g_wattnb [DD*D3];
__device__ __nv_bfloat16 g_waprojb[DD*DD];
__device__ __nv_bfloat16 g_wfcb   [EE*DD*FF];
__device__ __nv_bfloat16 g_wprojb [EE*FF*DD];
__device__ int   g_topidx[NTOK*TOPK];
__device__ float g_topw [NTOK*TOPK];
__device__ int   g_counts[EE];
__device__ int   g_offsets[EE+1];
__device__ int   g_cursor[EE];
__device__ int   g_pairtok[NPAIR];
__device__ float g_pairw [NPAIR];

// ---------------- helpers ----------------
__device__ __forceinline__ void mma_bf16(float c[4], unsigned a0, unsigned a1,
                                         unsigned a2, unsigned a3,
                                         unsigned b0, unsigned b1) {
    asm volatile(
        "mma.sync.aligned.m16n8k16.row.col.f32.bf16.bf16.f32 "
        "{%0,%1,%2,%3},{%4,%5,%6,%7},{%8,%9},{%0,%1,%2,%3};"
        : "+f"(c[0]), "+f"(c[1]), "+f"(c[2]), "+f"(c[3])
        : "r"(a0), "r"(a1), "r"(a2), "r"(a3), "r"(b0), "r"(b1));
}
__device__ __forceinline__ void ldsm4(unsigned& r0, unsigned& r1, unsigned& r2,
                                      unsigned& r3, unsigned a) {
    asm volatile("ldmatrix.sync.aligned.m8n8.x4.shared.b16 {%0,%1,%2,%3},[%4];"
                 : "=r"(r0), "=r"(r1), "=r"(r2), "=r"(r3) : "r"(a));
}
__device__ __forceinline__ void ldsm4t(unsigned& r0, unsigned& r1, unsigned& r2,
                                       unsigned& r3, unsigned a) {
    asm volatile("ldmatrix.sync.aligned.m8n8.x4.trans.shared.b16 {%0,%1,%2,%3},[%4];"
                 : "=r"(r0), "=r"(r1), "=r"(r2), "=r"(r3) : "r"(a));
}
__device__ __forceinline__ void cp16(void* smem_dst, const void* gsrc, bool valid) {
    unsigned dst = (unsigned)__cvta_generic_to_shared(smem_dst);
    int sz = valid ? 16 : 0;
    asm volatile("cp.async.cg.shared.global [%0], [%1], 16, %2;"
                 :: "r"(dst), "l"(gsrc), "r"(sz));
}
__device__ __forceinline__ void cp_commit() {
    asm volatile("cp.async.commit_group;");
}
__device__ __forceinline__ void cp_wait0() {
    asm volatile("cp.async.wait_group 0;" ::: "memory");
}
__device__ __forceinline__ void cp_wait1() {
    asm volatile("cp.async.wait_group 1;" ::: "memory");
}

// ---------------- fp32 -> bf16 weight conversion ----------------
__global__ void cvt_bf16(const float4* __restrict__ src, uint2* __restrict__ dst, int n4) {
    int i = blockIdx.x*blockDim.x + threadIdx.x;
    if (i >= n4) return;
    float4 a = src[i];
    __nv_bfloat162 h0 = __floats2bfloat162_rn(a.x, a.y);
    __nv_bfloat162 h1 = __floats2bfloat162_rn(a.z, a.w);
    dst[i] = make_uint2(*(unsigned*)&h0, *(unsigned*)&h1);
}

// ---------------- LayerNorm (fp32 in; optional fp32 out + bf16 out) ----------------
__global__ void ln_kernel(const float* __restrict__ x,
                          const float* __restrict__ g,
                          const float* __restrict__ b,
                          float* __restrict__ outf,
                          __nv_bfloat16* __restrict__ outb) {
    int row = blockIdx.x;
    int tid = threadIdx.x;
    const float* xr = x + (size_t)row*DD;
    float v[3];
    float s = 0.f, s2 = 0.f;
#pragma unroll
    for (int i = 0; i < 3; i++) {
        v[i] = xr[tid + i*256];
        s += v[i]; s2 += v[i]*v[i];
    }
    __shared__ float2 red[256];
    red[tid] = make_float2(s, s2);
    __syncthreads();
    for (int off = 128; off > 0; off >>= 1) {
        if (tid < off) {
            red[tid].x += red[tid+off].x;
            red[tid].y += red[tid+off].y;
        }
        __syncthreads();
    }
    float mu  = red[0].x * (1.0f/DD);
    float var = red[0].y * (1.0f/DD) - mu*mu;
    float inv = rsqrtf(var + 1e-5f);
#pragma unroll
    for (int i = 0; i < 3; i++) {
        int c = tid + i*256;
        float val = (v[i] - mu) * inv * g[c] + b[c];
        if (outf) outf[(size_t)row*DD + c] = val;
        outb[(size_t)row*DD + c] = __float2bfloat16(val);
    }
}

// ---------------- bf16 MMA GEMM: bf16 A + bf16 B, ldmatrix frags, 3-stage cp.async --------
// MODE 0: Cb = bf16(A@B + bias)                  (QKV)
// MODE 1: C = A@B + bias + resid; C2 = C (fp32)  (attn out proj + out init)
// MODE 2: Cb = bf16(gelu(gather(A)@B[e]+bias))   (MoE FC)
// MODE 3: atomic C[tok] += w*(A@B[e]+bias[e])    (MoE PROJ)
template<int MODE, int TM>
__global__ void __launch_bounds__(256)
mma_gemm(const __nv_bfloat16* __restrict__ A, const __nv_bfloat16* __restrict__ B,
         const float* __restrict__ bias, const float* __restrict__ resid,
         void* __restrict__ Cv, float* __restrict__ C2, int M, int N, int K) {
    constexpr int MI = TM/32;          // m16 tiles per warp
    constexpr int APAD = 24;           // bf16 elems per A row (48B: ldmatrix-clean)
    constexpr int BPAD = 136;          // bf16 elems per B row (272B: ldmatrix-clean)
    constexpr int ASTRIDE = TM*APAD;
    constexpr int BSTRIDE = 16*BPAD;
    constexpr int ACN = TM*2;          // 16B A chunks per stage

    int e = 0, seg = 0, cnt = M;
    if (MODE >= 2) {
        e = blockIdx.z;
        seg = g_offsets[e];
        cnt = g_offsets[e+1] - seg;
    }
    int rowBase = blockIdx.y * TM;
    if (rowBase >= cnt) return;
    int colBase = blockIdx.x * 128;
    const __nv_bfloat16* Bm = B + (size_t)e*K*N;
    const float* biasv = bias + (size_t)e*N;

    extern __shared__ __nv_bfloat16 smemb[];
    __nv_bfloat16* Asm = smemb;                 // 3 stages [TM][APAD]
    __nv_bfloat16* Bsm = smemb + 3*ASTRIDE;     // 3 stages [16][BPAD]
    __shared__ int sTok[TM];

    int tid = threadIdx.x;
    int lane = tid & 31, warp = tid >> 5;
    int wy = warp >> 2, wx = warp & 3;
    int g4 = lane >> 2, t4 = lane & 3;

    if (MODE == 2) {
        for (int i = tid; i < TM; i += 256)
            sTok[i] = (rowBase + i < cnt) ? g_pairtok[seg + rowBase + i] : -1;
        __syncthreads();
    }

    // A chunk coords: chunk tid -> (row, 8-elem half)
    int arow = tid >> 1, akh = (tid & 1) * 8;
    bool aact = (tid < ACN);
    const __nv_bfloat16* aptr = A;
    bool avalid = false;
    if (aact) {
        if (MODE == 2) {
            int tk = sTok[arow];
            avalid = (tk >= 0);
            aptr = A + (avalid ? (size_t)tk*K : 0) + akh;
        } else if (MODE == 3) {
            avalid = (rowBase + arow < cnt);
            aptr = A + (avalid ? (size_t)(seg + rowBase + arow)*K : 0) + akh;
        } else {
            avalid = true;
            aptr = A + (size_t)(rowBase + arow)*K + akh;
        }
    }
    // B chunk coords: 256 chunks (16 rows x 128 cols bf16), one per thread
    int brow = tid >> 4, bseg = (tid & 15) * 8;
    const __nv_bfloat16* bptr = Bm + (size_t)brow*N + colBase + bseg;

    float acc[MI][4][4] = {};
    int nt = K / 16;

    // prologue: tiles 0 and 1
#pragma unroll
    for (int p = 0; p < 2; p++) {
        int k0 = p * 16;
        if (aact) cp16(&Asm[p*ASTRIDE + arow*APAD + akh], aptr + k0, avalid);
        cp16(&Bsm[p*BSTRIDE + brow*BPAD + bseg], bptr + (size_t)k0*N, true);
        cp_commit();
    }

    // ldmatrix lane addressing (same index pattern for A and B)
    int lrow = lane & 15;
    int lcol = (lane >> 4) * 8;

    for (int kt = 0; kt < nt; kt++) {
        if (kt + 1 < nt) cp_wait1(); else cp_wait0();
        __syncthreads();
        if (kt + 2 < nt) {
            int st = (kt + 2) % 3;
            int k0 = (kt + 2) * 16;
            if (aact) cp16(&Asm[st*ASTRIDE + arow*APAD + akh], aptr + k0, avalid);
            cp16(&Bsm[st*BSTRIDE + brow*BPAD + bseg], bptr + (size_t)k0*N, true);
            cp_commit();
        }
        unsigned abase = (unsigned)__cvta_generic_to_shared(Asm + (kt % 3)*ASTRIDE);
        unsigned bbase = (unsigned)__cvta_generic_to_shared(Bsm + (kt % 3)*BSTRIDE);

        unsigned af[MI][4];
#pragma unroll
        for (int mi = 0; mi < MI; mi++) {
            unsigned addr = abase + ((wy*(TM/2) + mi*16 + lrow)*APAD + lcol)*2;
            ldsm4(af[mi][0], af[mi][1], af[mi][2], af[mi][3], addr);
        }
        unsigned bf[4][2];
#pragma unroll
        for (int nh = 0; nh < 2; nh++) {
            unsigned addr = bbase + (lrow*BPAD + wx*32 + nh*16 + lcol)*2;
            ldsm4t(bf[nh*2][0], bf[nh*2][1], bf[nh*2+1][0], bf[nh*2+1][1], addr);
        }
#pragma unroll
        for (int mi = 0; mi < MI; mi++)
#pragma unroll
            for (int ni = 0; ni < 4; ni++)
                mma_bf16(acc[mi][ni], af[mi][0], af[mi][1], af[mi][2], af[mi][3],
                         bf[ni][0], bf[ni][1]);
    }

    // epilogue
    __nv_bfloat16* Cb = (__nv_bfloat16*)Cv;
    float* C = (float*)Cv;
#pragma unroll
    for (int mi = 0; mi < MI; mi++) {
#pragma unroll
        for (int ci = 0; ci < 2; ci++) {
            int r = wy*(TM/2) + mi*16 + g4 + ci*8;
            int grow = rowBase + r;
            if (grow >= cnt) continue;
#pragma unroll
            for (int ni = 0; ni < 4; ni++) {
                int col = colBase + wx*32 + ni*8 + t4*2;
                float v0 = acc[mi][ni][ci*2 + 0];
                float v1 = acc[mi][ni][ci*2 + 1];
                if (MODE == 0) {
                    v0 += biasv[col]; v1 += biasv[col+1];
                    *(__nv_bfloat162*)&Cb[(size_t)grow*N + col] = __floats2bfloat162_rn(v0, v1);
                } else if (MODE == 1) {
                    const float2 rr = *(const float2*)&resid[(size_t)grow*N + col];
                    v0 += biasv[col]   + rr.x;
                    v1 += biasv[col+1] + rr.y;
                    *(float2*)&C [(size_t)grow*N + col] = make_float2(v0, v1);
                    *(float2*)&C2[(size_t)grow*N + col] = make_float2(v0, v1);
                } else if (MODE == 2) {
                    v0 += biasv[col]; v1 += biasv[col+1];
                    v0 = 0.5f*v0*(1.0f + erff(v0*0.70710678118654752f));
                    v1 = 0.5f*v1*(1.0f + erff(v1*0.70710678118654752f));
                    *(__nv_bfloat162*)&Cb[(size_t)(seg + grow)*N + col] = __floats2bfloat162_rn(v0, v1);
                } else {
                    int p = seg + grow;
                    int tok = g_pairtok[p];
                    float pw = g_pairw[p];
                    atomicAdd(&C[(size_t)tok*N + col],   pw*(v0 + biasv[col]));
                    atomicAdd(&C[(size_t)tok*N + col+1], pw*(v1 + biasv[col+1]));
                }
            }
        }
    }
}

// ---------------- bf16 tensor-core attention ----------------
// 128 threads = 4 warps; warp owns 16 query rows. smem K/V/P tiles [64][72] bf16.
__global__ void __launch_bounds__(128) attn_mma() {
    extern __shared__ __nv_bfloat16 sm16[];
    __nv_bfloat16* sK = sm16;             // [64][72]
    __nv_bfloat16* sV = sm16 + 64*72;     // [64][72]
    __nv_bfloat16* sP = sm16 + 2*64*72;   // [64][72]
    const unsigned* sKw = (const unsigned*)sK;
    const unsigned* sPw = (const unsigned*)sP;
    const unsigned short* sVh = (const unsigned short*)sV;

    int tid = threadIdx.x;
    int lane = tid & 31, warp = tid >> 5;
    int g4 = lane >> 2, t4 = lane & 3;
    int qt = (gridDim.x - 1) - blockIdx.x;     // heavy tiles first
    int bh = blockIdx.y;
    int b = bh / HH, h = bh % HH;
    size_t base = (size_t)(b*SS)*D3 + h*HDIM;

    int qr0 = qt*64 + warp*16 + g4;
    int qr1 = qr0 + 8;

    // Q fragments (bf16, unscaled; 1/8 folded into logits)
    unsigned aq[4][4];
    const __nv_bfloat16* Qr0 = g_qkvb + base + (size_t)qr0*D3;
    const __nv_bfloat16* Qr1 = g_qkvb + base + (size_t)qr1*D3;
#pragma unroll
    for (int kb = 0; kb < 4; kb++) {
        aq[kb][0] = *(const unsigned*)&Qr0[kb*16 + 2*t4];
        aq[kb][1] = *(const unsigned*)&Qr1[kb*16 + 2*t4];
        aq[kb][2] = *(const unsigned*)&Qr0[kb*16 + 2*t4 + 8];
        aq[kb][3] = *(const unsigned*)&Qr1[kb*16 + 2*t4 + 8];
    }

    float m0 = -1e30f, m1 = -1e30f, l0 = 0.f, l1 = 0.f;
    float o[8][4] = {};
    int r0w = warp*16 + g4;      // local P row

    for (int kt = 0; kt <= qt; kt++) {
        __syncthreads();
#pragma unroll
        for (int l = 0; l < 4; l++) {
            int idx = tid + l*128;
            int r = idx >> 3, c8 = (idx & 7) * 8;
            size_t rowp = base + (size_t)(kt*64 + r)*D3;
            *(uint4*)&sK[r*72 + c8] = *(const uint4*)&g_qkvb[rowp + DD + c8];
            *(uint4*)&sV[r*72 + c8] = *(const uint4*)&g_qkvb[rowp + 2*DD + c8];
        }
        __syncthreads();

        // S = Q K^T
        float s[8][4] = {};
#pragma unroll
        for (int kb = 0; kb < 4; kb++) {
#pragma unroll
            for (int jt = 0; jt < 8; jt++) {
                unsigned b0 = sKw[(jt*8 + g4)*36 + kb*8 + t4];
                unsigned b1 = sKw[(jt*8 + g4)*36 + kb*8 + t4 + 4];
                mma_bf16(s[jt], aq[kb][0], aq[kb][1], aq[kb][2], aq[kb][3], b0, b1);
            }
        }
#pragma unroll
        for (int jt = 0; jt < 8; jt++)
#pragma unroll
            for (int c = 0; c < 4; c++) s[jt][c] *= 0.125f;

        if (kt == qt) {
            int lr0 = warp*16 + g4, lr1 = lr0 + 8;
#pragma unroll
            for (int jt = 0; jt < 8; jt++) {
                int c = jt*8 + t4*2;
                if (c     > lr0) s[jt][0] = -1e30f;
                if (c + 1 > lr0) s[jt][1] = -1e30f;
                if (c     > lr1) s[jt][2] = -1e30f;
                if (c + 1 > lr1) s[jt][3] = -1e30f;
            }
        }
        // online softmax (stats across thread-quad)
        float rm0 = -1e30f, rm1 = -1e30f;
#pragma unroll
        for (int jt = 0; jt < 8; jt++) {
            rm0 = fmaxf(rm0, fmaxf(s[jt][0], s[jt][1]));
            rm1 = fmaxf(rm1, fmaxf(s[jt][2], s[jt][3]));
        }
        rm0 = fmaxf(rm0, __shfl_xor_sync(0xffffffffu, rm0, 1));
        rm0 = fmaxf(rm0, __shfl_xor_sync(0xffffffffu, rm0, 2));
        rm1 = fmaxf(rm1, __shfl_xor_sync(0xffffffffu, rm1, 1));
        rm1 = fmaxf(rm1, __shfl_xor_sync(0xffffffffu, rm1, 2));
        float nm0 = fmaxf(m0, rm0), nm1 = fmaxf(m1, rm1);
        float sc0 = __expf(m0 - nm0), sc1 = __expf(m1 - nm1);
        float ps0 = 0.f, ps1 = 0.f;
#pragma unroll
        for (int jt = 0; jt < 8; jt++) {
            float p0 = __expf(s[jt][0] - nm0);
            float p1 = __expf(s[jt][1] - nm0);
            float p2 = __expf(s[jt][2] - nm1);
            float p3 = __expf(s[jt][3] - nm1);
            ps0 += p0 + p1; ps1 += p2 + p3;
            ((__nv_bfloat162*)sP)[r0w*36     + jt*4 + t4] = __floats2bfloat162_rn(p0, p1);
            ((__nv_bfloat162*)sP)[(r0w+8)*36 + jt*4 + t4] = __floats2bfloat162_rn(p2, p3);
        }
        ps0 += __shfl_xor_sync(0xffffffffu, ps0, 1);
        ps0 += __shfl_xor_sync(0xffffffffu, ps0, 2);
        ps1 += __shfl_xor_sync(0xffffffffu, ps1, 1);
        ps1 += __shfl_xor_sync(0xffffffffu, ps1, 2);
        l0 = l0*sc0 + ps0;  m0 = nm0;
        l1 = l1*sc1 + ps1;  m1 = nm1;
#pragma unroll
        for (int dt = 0; dt < 8; dt++) {
            o[dt][0] *= sc0; o[dt][1] *= sc0;
            o[dt][2] *= sc1; o[dt][3] *= sc1;
        }
        __syncwarp();   // sP rows are warp-private

        // O += P V
#pragma unroll
        for (int kb = 0; kb < 4; kb++) {
            unsigned ap0 = sPw[r0w*36     + kb*8 + t4];
            unsigned ap1 = sPw[(r0w+8)*36 + kb*8 + t4];
            unsigned ap2 = sPw[r0w*36     + kb*8 + t4 + 4];
            unsigned ap3 = sPw[(r0w+8)*36 + kb*8 + t4 + 4];
            int krow = kb*16 + 2*t4;
#pragma unroll
            for (int dt = 0; dt < 8; dt++) {
                int dcol = dt*8 + g4;
                unsigned b0 = (unsigned)sVh[krow*72 + dcol]
                            | ((unsigned)sVh[(krow+1)*72 + dcol] << 16);
                unsigned b1 = (unsigned)sVh[(krow+8)*72 + dcol]
                            | ((unsigned)sVh[(krow+9)*72 + dcol] << 16);
                mma_bf16(o[dt], ap0, ap1, ap2, ap3, b0, b1);
            }
        }
    }

    // write ctx (bf16)
    float inv0 = 1.0f / l0, inv1 = 1.0f / l1;
#pragma unroll
    for (int dt = 0; dt < 8; dt++) {
        int col = h*HDIM + dt*8 + t4*2;
        *(__nv_bfloat162*)&g_ctxb[(size_t)(b*SS + qr0)*DD + col] =
            __floats2bfloat162_rn(o[dt][0]*inv0, o[dt][1]*inv0);
        *(__nv_bfloat162*)&g_ctxb[(size_t)(b*SS + qr1)*DD + col] =
            __floats2bfloat162_rn(o[dt][2]*inv1, o[dt][3]*inv1);
    }
}

// ---------------- Router + top-2 (fp32 x2) ----------------
__global__ void router_kernel(const float* __restrict__ x2, const float* __restrict__ w_router) {
    int gid  = blockIdx.x*blockDim.x + threadIdx.x;
    int warp = gid >> 5;
    int lane = gid & 31;
    if (warp >= NTOK) return;
    float p[EE] = {};
    const float* xr = x2 + (size_t)warp*DD;
    for (int d = lane; d < DD; d += 32) {
        float xv = xr[d];
#pragma unroll
        for (int e = 0; e < EE; e++) p[e] += xv * w_router[e*DD + d];
    }
#pragma unroll
    for (int off = 16; off > 0; off >>= 1)
#pragma unroll
        for (int e = 0; e < EE; e++)
            p[e] += __shfl_down_sync(0xffffffffu, p[e], off);
    if (lane == 0) {
        float mx = p[0];
#pragma unroll
        for (int e = 1; e < EE; e++) mx = fmaxf(mx, p[e]);
        float ex[EE];
#pragma unroll
        for (int e = 0; e < EE; e++) ex[e] = expf(p[e] - mx);
        int i0 = 0;
#pragma unroll
        for (int e = 1; e < EE; e++) if (ex[e] > ex[i0]) i0 = e;
        int i1 = (i0 == 0) ? 1 : 0;
#pragma unroll
        for (int e = 0; e < EE; e++) if (e != i0 && ex[e] > ex[i1]) i1 = e;
        float denom = ex[i0] + ex[i1];
        g_topidx[warp*2+0] = i0;  g_topw[warp*2+0] = ex[i0]/denom;
        g_topidx[warp*2+1] = i1;  g_topw[warp*2+1] = ex[i1]/denom;
        atomicAdd(&g_counts[i0], 1);
        atomicAdd(&g_counts[i1], 1);
    }
}

__global__ void offsets_kernel() {
    g_offsets[0] = 0;
    for (int e = 0; e < EE; e++) {
        g_offsets[e+1] = g_offsets[e] + g_counts[e];
        g_cursor[e] = 0;
    }
}

__global__ void fill_kernel() {
    int t = blockIdx.x*blockDim.x + threadIdx.x;
    if (t >= NTOK) return;
#pragma unroll
    for (int k = 0; k < TOPK; k++) {
        int e = g_topidx[t*2+k];
        int pos = g_offsets[e] + atomicAdd(&g_cursor[e], 1);
        g_pairtok[pos] = t;
        g_pairw[pos]   = g_topw[t*2+k];
    }
}

// ---------------- launch ----------------
extern "C" void kernel_launch(void* const* d_in, const int* in_sizes, int n_in,
                              void* d_out, int out_size) {
    const float* hidden     = (const float*)d_in[0];
    const float* ln1_g      = (const float*)d_in[1];
    const float* ln1_b      = (const float*)d_in[2];
    const float* w_attn     = (const float*)d_in[3];
    const float* b_attn     = (const float*)d_in[4];
    const float* w_attnproj = (const float*)d_in[5];
    const float* b_attnproj = (const float*)d_in[6];
    const float* ln2_g      = (const float*)d_in[7];
    const float* ln2_b      = (const float*)d_in[8];
    const float* w_router   = (const float*)d_in[9];
    const float* w_fc       = (const float*)d_in[10];
    const float* b_fc       = (const float*)d_in[11];
    const float* w_proj     = (const float*)d_in[12];
    const float* b_proj     = (const float*)d_in[13];
    float* out = (float*)d_out;

    __nv_bfloat16 *xln1b, *qkvb, *ctxb, *x2b, *ghb;
    __nv_bfloat16 *wattnb, *waprojb, *wfcb, *wprojb;
    float *hs, *x2;
    int* counts;
    cudaGetSymbolAddress((void**)&xln1b,   g_xln1b);
    cudaGetSymbolAddress((void**)&qkvb,    g_qkvb);
    cudaGetSymbolAddress((void**)&ctxb,    g_ctxb);
    cudaGetSymbolAddress((void**)&hs,      g_hs);
    cudaGetSymbolAddress((void**)&x2,      g_x2);
    cudaGetSymbolAddress((void**)&x2b,     g_x2b);
    cudaGetSymbolAddress((void**)&ghb,     g_hb);
    cudaGetSymbolAddress((void**)&wattnb,  g_wattnb);
    cudaGetSymbolAddress((void**)&waprojb, g_waprojb);
    cudaGetSymbolAddress((void**)&wfcb,    g_wfcb);
    cudaGetSymbolAddress((void**)&wprojb,  g_wprojb);
    cudaGetSymbolAddress((void**)&counts,  g_counts);

    const int SM128 = 3*(128*24 + 16*136)*2;  // 31488
    const int SM64  = 3*(64*24  + 16*136)*2;  // 22272
    const int SMATT = 3*64*72*2;              // 27648

    // weight conversions (bf16 caches)
    cvt_bf16<<<(DD*D3/4 + 255)/256, 256>>>((const float4*)w_attn, (uint2*)wattnb, DD*D3/4);
    cvt_bf16<<<(DD*DD/4 + 255)/256, 256>>>((const float4*)w_attnproj, (uint2*)waprojb, DD*DD/4);
    cvt_bf16<<<(EE*DD*FF/4 + 255)/256, 256>>>((const float4*)w_fc, (uint2*)wfcb, EE*DD*FF/4);
    cvt_bf16<<<(EE*FF*DD/4 + 255)/256, 256>>>((const float4*)w_proj, (uint2*)wprojb, EE*FF*DD/4);

    // attention sub-block
    ln_kernel<<<NTOK, 256>>>(hidden, ln1_g, ln1_b, nullptr, xln1b);
    mma_gemm<0,128><<<dim3(D3/128, NTOK/128, 1), 256, SM128>>>(
        xln1b, wattnb, b_attn, nullptr, qkvb, nullptr, NTOK, D3, DD);
    attn_mma<<<dim3(SS/64, BB*HH), 128, SMATT>>>();
    mma_gemm<1,64><<<dim3(DD/128, NTOK/64, 1), 256, SM64>>>(
        ctxb, waprojb, b_attnproj, hidden, hs, out, NTOK, DD, DD);

    // MoE sub-block
    ln_kernel<<<NTOK, 256>>>(hs, ln2_g, ln2_b, x2, x2b);
    cudaMemsetAsync(counts, 0, EE*sizeof(int));
    router_kernel<<<(NTOK*32)/256, 256>>>(x2, w_router);
    offsets_kernel<<<1,1>>>();
    fill_kernel<<<NTOK/256, 256>>>();
    mma_gemm<2,128><<<dim3(FF/128, NPAIR/128, EE), 256, SM128>>>(
        x2b, wfcb, b_fc, nullptr, ghb, nullptr, NPAIR, FF, DD);
    mma_gemm<3,64><<<dim3(DD/128, NPAIR/64, EE), 256, SM64>>>(
        ghb, wprojb, b_proj, nullptr, out, nullptr, NPAIR, DD, FF);
}

// round 8
// speedup vs baseline: 8.4154x; 1.1761x over previous
#include <cuda_runtime.h>
#include <cuda_bf16.h>
#include <math.h>

// Problem constants
#define BB 2
#define SS 1024
#define DD 768
#define HH 12
#define HDIM 64
#define EE 8
#define TOPK 2
#define FF 3072
#define NTOK (BB*SS)        // 2048
#define D3 (3*DD)           // 2304
#define NPAIR (NTOK*TOPK)   // 4096

// ---------------- device scratch ----------------
__device__ __nv_bfloat16 g_xln1b[NTOK*DD];
__device__ __nv_bfloat16 g_qkvb [NTOK*D3];
__device__ __nv_bfloat16 g_ctxb [NTOK*DD];
__device__ float         g_hs   [NTOK*DD];
__device__ float         g_x2   [NTOK*DD];
__device__ __nv_bfloat16 g_x2b  [NTOK*DD];
__device__ __nv_bfloat16 g_hb   [NPAIR*FF];
// bf16 weight caches (converted once per launch)
__device__ __nv_bfloat16 g_wattnb [DD*D3];
__device__ __nv_bfloat16 g_waprojb[DD*DD];
__device__ __nv_bfloat16 g_wfcb   [EE*DD*FF];
__device__ __nv_bfloat16 g_wprojb [EE*FF*DD];
__device__ int   g_topidx[NTOK*TOPK];
__device__ float g_topw [NTOK*TOPK];
__device__ int   g_counts[EE];
__device__ int   g_offsets[EE+1];
__device__ int   g_cursor[EE];
__device__ int   g_pairtok[NPAIR];
__device__ float g_pairw [NPAIR];

// ---------------- helpers ----------------
__device__ __forceinline__ void mma_bf16(float c[4], unsigned a0, unsigned a1,
                                         unsigned a2, unsigned a3,
                                         unsigned b0, unsigned b1) {
    asm volatile(
        "mma.sync.aligned.m16n8k16.row.col.f32.bf16.bf16.f32 "
        "{%0,%1,%2,%3},{%4,%5,%6,%7},{%8,%9},{%0,%1,%2,%3};"
        : "+f"(c[0]), "+f"(c[1]), "+f"(c[2]), "+f"(c[3])
        : "r"(a0), "r"(a1), "r"(a2), "r"(a3), "r"(b0), "r"(b1));
}
__device__ __forceinline__ void ldsm4(unsigned& r0, unsigned& r1, unsigned& r2,
                                      unsigned& r3, unsigned a) {
    asm volatile("ldmatrix.sync.aligned.m8n8.x4.shared.b16 {%0,%1,%2,%3},[%4];"
                 : "=r"(r0), "=r"(r1), "=r"(r2), "=r"(r3) : "r"(a));
}
__device__ __forceinline__ void ldsm4t(unsigned& r0, unsigned& r1, unsigned& r2,
                                       unsigned& r3, unsigned a) {
    asm volatile("ldmatrix.sync.aligned.m8n8.x4.trans.shared.b16 {%0,%1,%2,%3},[%4];"
                 : "=r"(r0), "=r"(r1), "=r"(r2), "=r"(r3) : "r"(a));
}
__device__ __forceinline__ void cp16(void* smem_dst, const void* gsrc, bool valid) {
    unsigned dst = (unsigned)__cvta_generic_to_shared(smem_dst);
    int sz = valid ? 16 : 0;
    asm volatile("cp.async.cg.shared.global [%0], [%1], 16, %2;"
                 :: "r"(dst), "l"(gsrc), "r"(sz));
}
__device__ __forceinline__ void cp_commit() {
    asm volatile("cp.async.commit_group;");
}
__device__ __forceinline__ void cp_wait0() {
    asm volatile("cp.async.wait_group 0;" ::: "memory");
}
__device__ __forceinline__ void cp_wait1() {
    asm volatile("cp.async.wait_group 1;" ::: "memory");
}

// ---------------- fp32 -> bf16 weight conversion (grid-stride, MLP 4) ----------------
__global__ void cvt_bf16(const float4* __restrict__ src, uint2* __restrict__ dst, int n4) {
    int stride = gridDim.x * blockDim.x;
#pragma unroll 4
    for (int i = blockIdx.x*blockDim.x + threadIdx.x; i < n4; i += stride) {
        float4 a = src[i];
        __nv_bfloat162 h0 = __floats2bfloat162_rn(a.x, a.y);
        __nv_bfloat162 h1 = __floats2bfloat162_rn(a.z, a.w);
        dst[i] = make_uint2(*(unsigned*)&h0, *(unsigned*)&h1);
    }
}

// ---------------- LayerNorm (fp32 in; optional fp32 out + bf16 out) ----------------
__global__ void ln_kernel(const float* __restrict__ x,
                          const float* __restrict__ g,
                          const float* __restrict__ b,
                          float* __restrict__ outf,
                          __nv_bfloat16* __restrict__ outb) {
    int row = blockIdx.x;
    int tid = threadIdx.x;
    const float* xr = x + (size_t)row*DD;
    float v[3];
    float s = 0.f, s2 = 0.f;
#pragma unroll
    for (int i = 0; i < 3; i++) {
        v[i] = xr[tid + i*256];
        s += v[i]; s2 += v[i]*v[i];
    }
    __shared__ float2 red[256];
    red[tid] = make_float2(s, s2);
    __syncthreads();
    for (int off = 128; off > 0; off >>= 1) {
        if (tid < off) {
            red[tid].x += red[tid+off].x;
            red[tid].y += red[tid+off].y;
        }
        __syncthreads();
    }
    float mu  = red[0].x * (1.0f/DD);
    float var = red[0].y * (1.0f/DD) - mu*mu;
    float inv = rsqrtf(var + 1e-5f);
#pragma unroll
    for (int i = 0; i < 3; i++) {
        int c = tid + i*256;
        float val = (v[i] - mu) * inv * g[c] + b[c];
        if (outf) outf[(size_t)row*DD + c] = val;
        outb[(size_t)row*DD + c] = __float2bfloat16(val);
    }
}

// ---------------- bf16 MMA GEMM: k-step 32, ldmatrix frags, 3-stage cp.async --------
// MODE 0: Cb = bf16(A@B + bias)                  (QKV)
// MODE 1: C = A@B + bias + resid; C2 = C (fp32)  (attn out proj + out init)
// MODE 2: Cb = bf16(gelu(gather(A)@B[e]+bias))   (MoE FC)
// MODE 3: atomic C[tok] += w*(A@B[e]+bias[e])    (MoE PROJ)
template<int MODE, int TM>
__global__ void __launch_bounds__(256)
mma_gemm(const __nv_bfloat16* __restrict__ A, const __nv_bfloat16* __restrict__ B,
         const float* __restrict__ bias, const float* __restrict__ resid,
         void* __restrict__ Cv, float* __restrict__ C2, int M, int N, int K) {
    constexpr int MI = TM/32;          // m16 tiles per warp
    constexpr int APAD = 40;           // bf16 per A row (80B: odd 16B units, ldmatrix-clean)
    constexpr int BPAD = 136;          // bf16 per B row (272B)
    constexpr int ASTRIDE = TM*APAD;
    constexpr int BSTRIDE = 32*BPAD;
    constexpr int ACH = TM*4;          // 16B A chunks per stage (32 k elems = 4 chunks/row)

    int e = 0, seg = 0, cnt = M;
    if (MODE >= 2) {
        e = blockIdx.z;
        seg = g_offsets[e];
        cnt = g_offsets[e+1] - seg;
    }
    int rowBase = blockIdx.y * TM;
    if (rowBase >= cnt) return;
    int colBase = blockIdx.x * 128;
    const __nv_bfloat16* Bm = B + (size_t)e*K*N;
    const float* biasv = bias + (size_t)e*N;

    extern __shared__ __nv_bfloat16 smemb[];
    __nv_bfloat16* Asm = smemb;                 // 3 stages [TM][APAD]
    __nv_bfloat16* Bsm = smemb + 3*ASTRIDE;     // 3 stages [32][BPAD]
    __shared__ int sTok[TM];

    int tid = threadIdx.x;
    int lane = tid & 31, warp = tid >> 5;
    int wy = warp >> 2, wx = warp & 3;
    int g4 = lane >> 2, t4 = lane & 3;

    if (MODE == 2) {
        for (int i = tid; i < TM; i += 256)
            sTok[i] = (rowBase + i < cnt) ? g_pairtok[seg + rowBase + i] : -1;
        __syncthreads();
    }

    // A chunk coords (ACH/256 chunks per thread)
    constexpr int ACT = (ACH + 255) / 256;
    int arow[ACT], akh[ACT];
    const __nv_bfloat16* aptr[ACT];
    bool avalid[ACT];
#pragma unroll
    for (int l = 0; l < ACT; l++) {
        int idx = tid + l*256;
        arow[l] = idx >> 2; akh[l] = (idx & 3) * 8;
        if (MODE == 2) {
            int tk = sTok[arow[l]];
            avalid[l] = (tk >= 0);
            aptr[l] = A + (avalid[l] ? (size_t)tk*K : 0) + akh[l];
        } else if (MODE == 3) {
            avalid[l] = (rowBase + arow[l] < cnt);
            aptr[l] = A + (avalid[l] ? (size_t)(seg + rowBase + arow[l])*K : 0) + akh[l];
        } else {
            avalid[l] = true;
            aptr[l] = A + (size_t)(rowBase + arow[l])*K + akh[l];
        }
    }
    // B chunk coords: 512 chunks (32 rows x 128 cols bf16), 2 per thread
    int brow[2], bseg[2];
    const __nv_bfloat16* bptr[2];
#pragma unroll
    for (int l = 0; l < 2; l++) {
        int idx = tid + l*256;
        brow[l] = idx >> 4; bseg[l] = (idx & 15) * 8;
        bptr[l] = Bm + (size_t)brow[l]*N + colBase + bseg[l];
    }

    float acc[MI][4][4] = {};
    int nt = K / 32;

    // prologue: tiles 0 and 1
#pragma unroll
    for (int p = 0; p < 2; p++) {
        int k0 = p * 32;
#pragma unroll
        for (int l = 0; l < ACT; l++)
            cp16(&Asm[p*ASTRIDE + arow[l]*APAD + akh[l]], aptr[l] + k0, avalid[l]);
#pragma unroll
        for (int l = 0; l < 2; l++)
            cp16(&Bsm[p*BSTRIDE + brow[l]*BPAD + bseg[l]], bptr[l] + (size_t)k0*N, true);
        cp_commit();
    }

    // ldmatrix lane addressing
    int lrow = lane & 15;
    int lcol = (lane >> 4) * 8;

    for (int kt = 0; kt < nt; kt++) {
        if (kt + 1 < nt) cp_wait1(); else cp_wait0();
        __syncthreads();
        if (kt + 2 < nt) {
            int st = (kt + 2) % 3;
            int k0 = (kt + 2) * 32;
#pragma unroll
            for (int l = 0; l < ACT; l++)
                cp16(&Asm[st*ASTRIDE + arow[l]*APAD + akh[l]], aptr[l] + k0, avalid[l]);
#pragma unroll
            for (int l = 0; l < 2; l++)
                cp16(&Bsm[st*BSTRIDE + brow[l]*BPAD + bseg[l]], bptr[l] + (size_t)k0*N, true);
            cp_commit();
        }
        unsigned abase = (unsigned)__cvta_generic_to_shared(Asm + (kt % 3)*ASTRIDE);
        unsigned bbase = (unsigned)__cvta_generic_to_shared(Bsm + (kt % 3)*BSTRIDE);

#pragma unroll
        for (int ks = 0; ks < 32; ks += 16) {
            unsigned af[MI][4];
#pragma unroll
            for (int mi = 0; mi < MI; mi++) {
                unsigned addr = abase + ((wy*(TM/2) + mi*16 + lrow)*APAD + ks + lcol)*2;
                ldsm4(af[mi][0], af[mi][1], af[mi][2], af[mi][3], addr);
            }
            unsigned bf[4][2];
#pragma unroll
            for (int nh = 0; nh < 2; nh++) {
                unsigned addr = bbase + ((ks + lrow)*BPAD + wx*32 + nh*16 + lcol)*2;
                ldsm4t(bf[nh*2][0], bf[nh*2][1], bf[nh*2+1][0], bf[nh*2+1][1], addr);
            }
#pragma unroll
            for (int mi = 0; mi < MI; mi++)
#pragma unroll
                for (int ni = 0; ni < 4; ni++)
                    mma_bf16(acc[mi][ni], af[mi][0], af[mi][1], af[mi][2], af[mi][3],
                             bf[ni][0], bf[ni][1]);
        }
    }

    // epilogue
    __nv_bfloat16* Cb = (__nv_bfloat16*)Cv;
    float* C = (float*)Cv;
#pragma unroll
    for (int mi = 0; mi < MI; mi++) {
#pragma unroll
        for (int ci = 0; ci < 2; ci++) {
            int r = wy*(TM/2) + mi*16 + g4 + ci*8;
            int grow = rowBase + r;
            if (grow >= cnt) continue;
#pragma unroll
            for (int ni = 0; ni < 4; ni++) {
                int col = colBase + wx*32 + ni*8 + t4*2;
                float v0 = acc[mi][ni][ci*2 + 0];
                float v1 = acc[mi][ni][ci*2 + 1];
                if (MODE == 0) {
                    v0 += biasv[col]; v1 += biasv[col+1];
                    *(__nv_bfloat162*)&Cb[(size_t)grow*N + col] = __floats2bfloat162_rn(v0, v1);
                } else if (MODE == 1) {
                    const float2 rr = *(const float2*)&resid[(size_t)grow*N + col];
                    v0 += biasv[col]   + rr.x;
                    v1 += biasv[col+1] + rr.y;
                    *(float2*)&C [(size_t)grow*N + col] = make_float2(v0, v1);
                    *(float2*)&C2[(size_t)grow*N + col] = make_float2(v0, v1);
                } else if (MODE == 2) {
                    v0 += biasv[col]; v1 += biasv[col+1];
                    v0 = 0.5f*v0*(1.0f + erff(v0*0.70710678118654752f));
                    v1 = 0.5f*v1*(1.0f + erff(v1*0.70710678118654752f));
                    *(__nv_bfloat162*)&Cb[(size_t)(seg + grow)*N + col] = __floats2bfloat162_rn(v0, v1);
                } else {
                    int p = seg + grow;
                    int tok = g_pairtok[p];
                    float pw = g_pairw[p];
                    atomicAdd(&C[(size_t)tok*N + col],   pw*(v0 + biasv[col]));
                    atomicAdd(&C[(size_t)tok*N + col+1], pw*(v1 + biasv[col+1]));
                }
            }
        }
    }
}

// ---------------- bf16 tensor-core attention ----------------
// 128 threads = 4 warps; warp owns 16 query rows. smem K/V/P tiles [64][72] bf16.
__global__ void __launch_bounds__(128) attn_mma() {
    extern __shared__ __nv_bfloat16 sm16[];
    __nv_bfloat16* sK = sm16;             // [64][72]
    __nv_bfloat16* sV = sm16 + 64*72;     // [64][72]
    __nv_bfloat16* sP = sm16 + 2*64*72;   // [64][72]
    const unsigned* sKw = (const unsigned*)sK;
    const unsigned* sPw = (const unsigned*)sP;
    const unsigned short* sVh = (const unsigned short*)sV;

    int tid = threadIdx.x;
    int lane = tid & 31, warp = tid >> 5;
    int g4 = lane >> 2, t4 = lane & 3;
    int qt = (gridDim.x - 1) - blockIdx.x;     // heavy tiles first
    int bh = blockIdx.y;
    int b = bh / HH, h = bh % HH;
    size_t base = (size_t)(b*SS)*D3 + h*HDIM;

    int qr0 = qt*64 + warp*16 + g4;
    int qr1 = qr0 + 8;

    // Q fragments (bf16, unscaled; 1/8 folded into logits)
    unsigned aq[4][4];
    const __nv_bfloat16* Qr0 = g_qkvb + base + (size_t)qr0*D3;
    const __nv_bfloat16* Qr1 = g_qkvb + base + (size_t)qr1*D3;
#pragma unroll
    for (int kb = 0; kb < 4; kb++) {
        aq[kb][0] = *(const unsigned*)&Qr0[kb*16 + 2*t4];
        aq[kb][1] = *(const unsigned*)&Qr1[kb*16 + 2*t4];
        aq[kb][2] = *(const unsigned*)&Qr0[kb*16 + 2*t4 + 8];
        aq[kb][3] = *(const unsigned*)&Qr1[kb*16 + 2*t4 + 8];
    }

    float m0 = -1e30f, m1 = -1e30f, l0 = 0.f, l1 = 0.f;
    float o[8][4] = {};
    int r0w = warp*16 + g4;      // local P row

    for (int kt = 0; kt <= qt; kt++) {
        __syncthreads();
#pragma unroll
        for (int l = 0; l < 4; l++) {
            int idx = tid + l*128;
            int r = idx >> 3, c8 = (idx & 7) * 8;
            size_t rowp = base + (size_t)(kt*64 + r)*D3;
            *(uint4*)&sK[r*72 + c8] = *(const uint4*)&g_qkvb[rowp + DD + c8];
            *(uint4*)&sV[r*72 + c8] = *(const uint4*)&g_qkvb[rowp + 2*DD + c8];
        }
        __syncthreads();

        // S = Q K^T
        float s[8][4] = {};
#pragma unroll
        for (int kb = 0; kb < 4; kb++) {
#pragma unroll
            for (int jt = 0; jt < 8; jt++) {
                unsigned b0 = sKw[(jt*8 + g4)*36 + kb*8 + t4];
                unsigned b1 = sKw[(jt*8 + g4)*36 + kb*8 + t4 + 4];
                mma_bf16(s[jt], aq[kb][0], aq[kb][1], aq[kb][2], aq[kb][3], b0, b1);
            }
        }
#pragma unroll
        for (int jt = 0; jt < 8; jt++)
#pragma unroll
            for (int c = 0; c < 4; c++) s[jt][c] *= 0.125f;

        if (kt == qt) {
            int lr0 = warp*16 + g4, lr1 = lr0 + 8;
#pragma unroll
            for (int jt = 0; jt < 8; jt++) {
                int c = jt*8 + t4*2;
                if (c     > lr0) s[jt][0] = -1e30f;
                if (c + 1 > lr0) s[jt][1] = -1e30f;
                if (c     > lr1) s[jt][2] = -1e30f;
                if (c + 1 > lr1) s[jt][3] = -1e30f;
            }
        }
        // online softmax (stats across thread-quad)
        float rm0 = -1e30f, rm1 = -1e30f;
#pragma unroll
        for (int jt = 0; jt < 8; jt++) {
            rm0 = fmaxf(rm0, fmaxf(s[jt][0], s[jt][1]));
            rm1 = fmaxf(rm1, fmaxf(s[jt][2], s[jt][3]));
        }
        rm0 = fmaxf(rm0, __shfl_xor_sync(0xffffffffu, rm0, 1));
        rm0 = fmaxf(rm0, __shfl_xor_sync(0xffffffffu, rm0, 2));
        rm1 = fmaxf(rm1, __shfl_xor_sync(0xffffffffu, rm1, 1));
        rm1 = fmaxf(rm1, __shfl_xor_sync(0xffffffffu, rm1, 2));
        float nm0 = fmaxf(m0, rm0), nm1 = fmaxf(m1, rm1);
        float sc0 = __expf(m0 - nm0), sc1 = __expf(m1 - nm1);
        float ps0 = 0.f, ps1 = 0.f;
#pragma unroll
        for (int jt = 0; jt < 8; jt++) {
            float p0 = __expf(s[jt][0] - nm0);
            float p1 = __expf(s[jt][1] - nm0);
            float p2 = __expf(s[jt][2] - nm1);
            float p3 = __expf(s[jt][3] - nm1);
            ps0 += p0 + p1; ps1 += p2 + p3;
            ((__nv_bfloat162*)sP)[r0w*36     + jt*4 + t4] = __floats2bfloat162_rn(p0, p1);
            ((__nv_bfloat162*)sP)[(r0w+8)*36 + jt*4 + t4] = __floats2bfloat162_rn(p2, p3);
        }
        ps0 += __shfl_xor_sync(0xffffffffu, ps0, 1);
        ps0 += __shfl_xor_sync(0xffffffffu, ps0, 2);
        ps1 += __shfl_xor_sync(0xffffffffu, ps1, 1);
        ps1 += __shfl_xor_sync(0xffffffffu, ps1, 2);
        l0 = l0*sc0 + ps0;  m0 = nm0;
        l1 = l1*sc1 + ps1;  m1 = nm1;
#pragma unroll
        for (int dt = 0; dt < 8; dt++) {
            o[dt][0] *= sc0; o[dt][1] *= sc0;
            o[dt][2] *= sc1; o[dt][3] *= sc1;
        }
        __syncwarp();   // sP rows are warp-private

        // O += P V
#pragma unroll
        for (int kb = 0; kb < 4; kb++) {
            unsigned ap0 = sPw[r0w*36     + kb*8 + t4];
            unsigned ap1 = sPw[(r0w+8)*36 + kb*8 + t4];
            unsigned ap2 = sPw[r0w*36     + kb*8 + t4 + 4];
            unsigned ap3 = sPw[(r0w+8)*36 + kb*8 + t4 + 4];
            int krow = kb*16 + 2*t4;
#pragma unroll
            for (int dt = 0; dt < 8; dt++) {
                int dcol = dt*8 + g4;
                unsigned b0 = (unsigned)sVh[krow*72 + dcol]
                            | ((unsigned)sVh[(krow+1)*72 + dcol] << 16);
                unsigned b1 = (unsigned)sVh[(krow+8)*72 + dcol]
                            | ((unsigned)sVh[(krow+9)*72 + dcol] << 16);
                mma_bf16(o[dt], ap0, ap1, ap2, ap3, b0, b1);
            }
        }
    }

    // write ctx (bf16)
    float inv0 = 1.0f / l0, inv1 = 1.0f / l1;
#pragma unroll
    for (int dt = 0; dt < 8; dt++) {
        int col = h*HDIM + dt*8 + t4*2;
        *(__nv_bfloat162*)&g_ctxb[(size_t)(b*SS + qr0)*DD + col] =
            __floats2bfloat162_rn(o[dt][0]*inv0, o[dt][1]*inv0);
        *(__nv_bfloat162*)&g_ctxb[(size_t)(b*SS + qr1)*DD + col] =
            __floats2bfloat162_rn(o[dt][2]*inv1, o[dt][3]*inv1);
    }
}

// ---------------- Router + top-2 (fp32 x2) ----------------
__global__ void router_kernel(const float* __restrict__ x2, const float* __restrict__ w_router) {
    int gid  = blockIdx.x*blockDim.x + threadIdx.x;
    int warp = gid >> 5;
    int lane = gid & 31;
    if (warp >= NTOK) return;
    float p[EE] = {};
    const float* xr = x2 + (size_t)warp*DD;
    for (int d = lane; d < DD; d += 32) {
        float xv = xr[d];
#pragma unroll
        for (int e = 0; e < EE; e++) p[e] += xv * w_router[e*DD + d];
    }
#pragma unroll
    for (int off = 16; off > 0; off >>= 1)
#pragma unroll
        for (int e = 0; e < EE; e++)
            p[e] += __shfl_down_sync(0xffffffffu, p[e], off);
    if (lane == 0) {
        float mx = p[0];
#pragma unroll
        for (int e = 1; e < EE; e++) mx = fmaxf(mx, p[e]);
        float ex[EE];
#pragma unroll
        for (int e = 0; e < EE; e++) ex[e] = expf(p[e] - mx);
        int i0 = 0;
#pragma unroll
        for (int e = 1; e < EE; e++) if (ex[e] > ex[i0]) i0 = e;
        int i1 = (i0 == 0) ? 1 : 0;
#pragma unroll
        for (int e = 0; e < EE; e++) if (e != i0 && ex[e] > ex[i1]) i1 = e;
        float denom = ex[i0] + ex[i1];
        g_topidx[warp*2+0] = i0;  g_topw[warp*2+0] = ex[i0]/denom;
        g_topidx[warp*2+1] = i1;  g_topw[warp*2+1] = ex[i1]/denom;
        atomicAdd(&g_counts[i0], 1);
        atomicAdd(&g_counts[i1], 1);
    }
}

__global__ void offsets_kernel() {
    g_offsets[0] = 0;
    for (int e = 0; e < EE; e++) {
        g_offsets[e+1] = g_offsets[e] + g_counts[e];
        g_cursor[e] = 0;
    }
}

__global__ void fill_kernel() {
    int t = blockIdx.x*blockDim.x + threadIdx.x;
    if (t >= NTOK) return;
#pragma unroll
    for (int k = 0; k < TOPK; k++) {
        int e = g_topidx[t*2+k];
        int pos = g_offsets[e] + atomicAdd(&g_cursor[e], 1);
        g_pairtok[pos] = t;
        g_pairw[pos]   = g_topw[t*2+k];
    }
}

// ---------------- launch ----------------
extern "C" void kernel_launch(void* const* d_in, const int* in_sizes, int n_in,
                              void* d_out, int out_size) {
    const float* hidden     = (const float*)d_in[0];
    const float* ln1_g      = (const float*)d_in[1];
    const float* ln1_b      = (const float*)d_in[2];
    const float* w_attn     = (const float*)d_in[3];
    const float* b_attn     = (const float*)d_in[4];
    const float* w_attnproj = (const float*)d_in[5];
    const float* b_attnproj = (const float*)d_in[6];
    const float* ln2_g      = (const float*)d_in[7];
    const float* ln2_b      = (const float*)d_in[8];
    const float* w_router   = (const float*)d_in[9];
    const float* w_fc       = (const float*)d_in[10];
    const float* b_fc       = (const float*)d_in[11];
    const float* w_proj     = (const float*)d_in[12];
    const float* b_proj     = (const float*)d_in[13];
    float* out = (float*)d_out;

    __nv_bfloat16 *xln1b, *qkvb, *ctxb, *x2b, *ghb;
    __nv_bfloat16 *wattnb, *waprojb, *wfcb, *wprojb;
    float *hs, *x2;
    int* counts;
    cudaGetSymbolAddress((void**)&xln1b,   g_xln1b);
    cudaGetSymbolAddress((void**)&qkvb,    g_qkvb);
    cudaGetSymbolAddress((void**)&ctxb,    g_ctxb);
    cudaGetSymbolAddress((void**)&hs,      g_hs);
    cudaGetSymbolAddress((void**)&x2,      g_x2);
    cudaGetSymbolAddress((void**)&x2b,     g_x2b);
    cudaGetSymbolAddress((void**)&ghb,     g_hb);
    cudaGetSymbolAddress((void**)&wattnb,  g_wattnb);
    cudaGetSymbolAddress((void**)&waprojb, g_waprojb);
    cudaGetSymbolAddress((void**)&wfcb,    g_wfcb);
    cudaGetSymbolAddress((void**)&wprojb,  g_wprojb);
    cudaGetSymbolAddress((void**)&counts,  g_counts);

    const int SM128 = 3*(128*40 + 32*136)*2;  // 56832
    const int SM64  = 3*(64*40  + 32*136)*2;  // 41472
    const int SMATT = 3*64*72*2;              // 27648

    cudaFuncSetAttribute((const void*)mma_gemm<0,128>, cudaFuncAttributeMaxDynamicSharedMemorySize, SM128);
    cudaFuncSetAttribute((const void*)mma_gemm<1,64>,  cudaFuncAttributeMaxDynamicSharedMemorySize, SM64);
    cudaFuncSetAttribute((const void*)mma_gemm<2,128>, cudaFuncAttributeMaxDynamicSharedMemorySize, SM128);
    cudaFuncSetAttribute((const void*)mma_gemm<3,64>,  cudaFuncAttributeMaxDynamicSharedMemorySize, SM64);

    // weight conversions (bf16 caches); grid-stride, capped grid
    auto cvtgrid = [](int n4) { int g = (n4 + 255)/256; return g < 1184 ? g : 1184; };
    cvt_bf16<<<cvtgrid(DD*D3/4), 256>>>((const float4*)w_attn, (uint2*)wattnb, DD*D3/4);
    cvt_bf16<<<cvtgrid(DD*DD/4), 256>>>((const float4*)w_attnproj, (uint2*)waprojb, DD*DD/4);
    cvt_bf16<<<cvtgrid(EE*DD*FF/4), 256>>>((const float4*)w_fc, (uint2*)wfcb, EE*DD*FF/4);
    cvt_bf16<<<cvtgrid(EE*FF*DD/4), 256>>>((const float4*)w_proj, (uint2*)wprojb, EE*FF*DD/4);

    // attention sub-block
    ln_kernel<<<NTOK, 256>>>(hidden, ln1_g, ln1_b, nullptr, xln1b);
    mma_gemm<0,128><<<dim3(D3/128, NTOK/128, 1), 256, SM128>>>(
        xln1b, wattnb, b_attn, nullptr, qkvb, nullptr, NTOK, D3, DD);
    attn_mma<<<dim3(SS/64, BB*HH), 128, SMATT>>>();
    mma_gemm<1,64><<<dim3(DD/128, NTOK/64, 1), 256, SM64>>>(
        ctxb, waprojb, b_attnproj, hidden, hs, out, NTOK, DD, DD);

    // MoE sub-block
    ln_kernel<<<NTOK, 256>>>(hs, ln2_g, ln2_b, x2, x2b);
    cudaMemsetAsync(counts, 0, EE*sizeof(int));
    router_kernel<<<(NTOK*32)/256, 256>>>(x2, w_router);
    offsets_kernel<<<1,1>>>();
    fill_kernel<<<NTOK/256, 256>>>();
    mma_gemm<2,128><<<dim3(FF/128, NPAIR/128, EE), 256, SM128>>>(
        x2b, wfcb, b_fc, nullptr, ghb, nullptr, NPAIR, FF, DD);
    mma_gemm<3,64><<<dim3(DD/128, NPAIR/64, EE), 256, SM64>>>(
        ghb, wprojb, b_proj, nullptr, out, nullptr, NPAIR, DD, FF);
}